// round 10
// baseline (speedup 1.0000x reference)
#include <cuda_runtime.h>
#include <math.h>
#include <stdint.h>

#define Bn 16
#define Cc 32
#define Hh 128
#define Ww 128
#define HW (Hh*Ww)
#define CHW (Cc*HW)
#define NTOT (Bn*CHW)

// block tile: 8 out rows x 32 out cols = 256 px; halo 10x34 = 340 A rows
#define THREADS 256
#define NROWS 340

#define RS     144                    // padded SMEM row stride (128 data + 16)
#define B_TAP  (32*RS)                // 4608
#define B_SZ   (9*B_TAP)              // 41472
#define B_OFF  0
#define A_OFF  B_SZ
#define A_SZ   (NROWS*RS)             // 48960
#define SMEM_T (B_SZ + A_SZ)          // 90432 -> 2 blocks/SM

// transpose buffer (reuses B region after mainloop): 256 px * 33 floats
#define XP_OFF 0

// global A-row images: [t(4)][b*HW + pix] rows of 128B ([hi 32ci | lo 32ci] bf16), dense
__device__ uint4 g_Arows[(size_t)4*Bn*HW*8];

// B padded-dense: state [t(3)][half(2)][tap(9)][co(32)][144B]; out [tap][co][144B]
__device__ __align__(16) unsigned short g_Bst[3*2*20736];   // 3*82944 B
__device__ __align__(16) unsigned short g_Bout[20736];      // 41472 B
__device__ float g_bcomb[64];
__device__ float g_bout[32];
__device__ float g_invtau[64];

// ---------------- helpers ----------------
__device__ __forceinline__ uint32_t smem_u32(const void* p) {
    uint32_t a;
    asm("{ .reg .u64 t; cvta.to.shared.u64 t, %1; cvt.u32.u64 %0, t; }" : "=r"(a) : "l"(p));
    return a;
}
__device__ __forceinline__ void bf16split(float v, unsigned short& h, unsigned short& l) {
    asm("cvt.rn.bf16.f32 %0, %1;" : "=h"(h) : "f"(v));
    float hf;
    asm("cvt.f32.bf16 %0, %1;" : "=f"(hf) : "h"(h));
    asm("cvt.rn.bf16.f32 %0, %1;" : "=h"(l) : "f"(v - hf));
}
__device__ __forceinline__ float fast_tanh(float x) {
    float e, r;
    asm("ex2.approx.f32 %0, %1;" : "=f"(e) : "f"(x * 2.8853900817779268f));
    asm("rcp.approx.f32 %0, %1;" : "=f"(r) : "f"(e + 1.f));
    return fmaf(-2.f, r, 1.f);
}
__device__ __forceinline__ void mma16816(float* c,
    uint32_t a0, uint32_t a1, uint32_t a2, uint32_t a3, uint32_t b0, uint32_t b1)
{
    asm volatile(
        "mma.sync.aligned.m16n8k16.row.col.f32.bf16.bf16.f32 "
        "{%0,%1,%2,%3}, {%4,%5,%6,%7}, {%8,%9}, {%0,%1,%2,%3};"
        : "+f"(c[0]), "+f"(c[1]), "+f"(c[2]), "+f"(c[3])
        : "r"(a0), "r"(a1), "r"(a2), "r"(a3), "r"(b0), "r"(b1));
}
__device__ __forceinline__ void ldsm4(uint32_t* r, uint32_t addr) {
    asm volatile("ldmatrix.sync.aligned.m8n8.x4.shared.b16 {%0,%1,%2,%3}, [%4];"
        : "=r"(r[0]), "=r"(r[1]), "=r"(r[2]), "=r"(r[3]) : "r"(addr));
}
__device__ __forceinline__ void cp16(uint32_t smdst, const void* gsrc) {
    asm volatile("cp.async.cg.shared.global [%0], [%1], 16;" :: "r"(smdst), "l"(gsrc));
}
#define CP_COMMIT() asm volatile("cp.async.commit_group;" ::: "memory")
#define CP_WAIT0()  asm volatile("cp.async.wait_group 0;" ::: "memory")

// ---------------- prep ----------------
__global__ void prep_kernel(
    const float* __restrict__ W_in_e, const float* __restrict__ b_in_e,
    const float* __restrict__ W_in_i, const float* __restrict__ b_in_i,
    const float* __restrict__ W_e_e,  const float* __restrict__ b_e_e,
    const float* __restrict__ W_e_i,  const float* __restrict__ b_e_i,
    const float* __restrict__ W_e_out,const float* __restrict__ b_e_out,
    const float* __restrict__ W_i_e,  const float* __restrict__ b_i_e,
    const float* __restrict__ W_i_i,  const float* __restrict__ b_i_i,
    const float* __restrict__ tau_e,  const float* __restrict__ tau_i)
{
    int fid = blockIdx.x * 256 + threadIdx.x;
    if (fid < 3*9*64*32) {
        int ci  = fid & 31;
        int r   = fid >> 5;
        int co  = r & 63;  r >>= 6;
        int tau = r % 9;
        int t   = r / 9;
        int src = (co & 31) * 288 + ci * 9 + tau;   // OIHW
        float w;
        if (t == 0)      w = (co < 32) ? W_in_e[src] : W_in_i[src];
        else if (t == 1) w = fmaxf((co < 32) ? W_e_e[src] : W_e_i[src], 0.f);
        else             w = -fmaxf((co < 32) ? W_i_e[src] : W_i_i[src], 0.f);
        unsigned short h, l;
        bf16split(w, h, l);
        uint32_t base = (uint32_t)t*82944 + (uint32_t)(co >> 5)*41472
                      + (uint32_t)tau*B_TAP + (uint32_t)(co & 31)*RS;
        g_Bst[(base + (uint32_t)ci*2) >> 1]       = h;
        g_Bst[(base + 64u + (uint32_t)ci*2) >> 1] = l;
    } else if (fid < 3*9*64*32 + 9*32*32) {
        int f2  = fid - 3*9*64*32;
        int ci  = f2 & 31;
        int r   = f2 >> 5;
        int co  = r & 31;
        int tau = r >> 5;
        float w = fmaxf(W_e_out[co*288 + ci*9 + tau], 0.f);
        unsigned short h, l;
        bf16split(w, h, l);
        uint32_t base = (uint32_t)tau*B_TAP + (uint32_t)co*RS;
        g_Bout[(base + (uint32_t)ci*2) >> 1]       = h;
        g_Bout[(base + 64u + (uint32_t)ci*2) >> 1] = l;
    }
    if (blockIdx.x == 0 && threadIdx.x < 64) {
        int co = threadIdx.x;
        if (co < 32) {
            g_bcomb[co]  = b_in_e[co] + fmaxf(b_e_e[co], 0.f) - fmaxf(b_i_e[co], 0.f);
            g_invtau[co] = 1.f / fmaxf(tau_e[co], 1.f);
            g_bout[co]   = fmaxf(b_e_out[co], 0.f);
        } else {
            int c = co - 32;
            g_bcomb[co]  = b_in_i[c] + fmaxf(b_e_i[c], 0.f) - fmaxf(b_i_i[c], 0.f);
            g_invtau[co] = 1.f / fmaxf(tau_i[c], 1.f);
        }
    }
}

// ---------------- convert: NCHW fp32 -> per-pixel 128B bf16 hi/lo rows ----------------
__global__ void __launch_bounds__(256)
convert_kernel(const float* __restrict__ x, const float* __restrict__ he,
               const float* __restrict__ hi)
{
    int gidx = blockIdx.x * 256 + threadIdx.x;
    int t = gidx / (Bn*HW);
    int p = gidx - t * (Bn*HW);
    int b = p / HW;
    int pix = p - b * HW;
    const float* src = (t == 0 ? x : (t == 1 ? he : hi)) + (size_t)b * CHW + pix;
    uint4* dst = g_Arows + ((size_t)t * (Bn*HW) + p) * 8;

    uint32_t hw[16], lw[16];
    #pragma unroll
    for (int k = 0; k < 16; k++) {
        float v0 = src[(size_t)(2*k)   * HW];
        float v1 = src[(size_t)(2*k+1) * HW];
        unsigned short h0, l0, h1, l1;
        bf16split(v0, h0, l0);
        bf16split(v1, h1, l1);
        hw[k] = (uint32_t)h0 | ((uint32_t)h1 << 16);
        lw[k] = (uint32_t)l0 | ((uint32_t)l1 << 16);
    }
    #pragma unroll
    for (int j = 0; j < 4; j++) {
        dst[j]     = make_uint4(hw[4*j], hw[4*j+1], hw[4*j+2], hw[4*j+3]);
        dst[4 + j] = make_uint4(lw[4*j], lw[4*j+1], lw[4*j+2], lw[4*j+3]);
    }
}

// A tile copy (cp.async, zero halo), padded-dense SMEM rows
__device__ __forceinline__ void stage_A(char* sm, uint32_t smb,
                                        int t, int b, int ty0, int tx0, int tid)
{
    const char* gbase = (const char*)g_Arows + ((size_t)t * (Bn*HW) + (size_t)b * HW) * 128;
    for (int i = tid; i < NROWS*8; i += THREADS) {
        int r = i >> 3, c = i & 7;
        int ry = r / 34, rx = r - ry*34;
        int gy = ty0 + ry - 1, gx = tx0 + rx - 1;
        uint32_t dst = smb + A_OFF + (uint32_t)r*RS + (uint32_t)c*16;
        if (((unsigned)gy < 128u) && ((unsigned)gx < 128u))
            cp16(dst, gbase + ((size_t)(gy*128 + gx))*128 + c*16);
        else
            *(uint4*)(sm + (dst - smb)) = make_uint4(0,0,0,0);
    }
}

// mainloop body: N=32, 9 taps; tap-invariant lane bases, immediate offsets
__device__ __forceinline__ void conv_tap_loop(
    float acc[2][4][4], const uint32_t laneA0, const uint32_t laneA1, const uint32_t laneB)
{
    #pragma unroll 1
    for (int tap = 0; tap < 9; tap++) {
        const int soff = ((tap/3) - 1) * (34*RS) + ((tap % 3) - 1) * RS;
        const uint32_t aA0 = laneA0 + soff;
        const uint32_t aA1 = laneA1 + soff;
        const uint32_t bB  = laneB + (uint32_t)tap * B_TAP;

        uint32_t Ah0[2][4], Ah1[2][4], Al0[2][4], Al1[2][4];
        ldsm4(Ah0[0], aA0 + 0);  ldsm4(Ah1[0], aA0 + 32);
        ldsm4(Al0[0], aA0 + 64); ldsm4(Al1[0], aA0 + 96);
        ldsm4(Ah0[1], aA1 + 0);  ldsm4(Ah1[1], aA1 + 32);
        ldsm4(Al0[1], aA1 + 64); ldsm4(Al1[1], aA1 + 96);

        uint32_t bf0[8], bf1[8], bf2[8], bf3[8];
        ldsm4(bf0,     bB + 0);          ldsm4(bf0 + 4, bB + 2304 + 0);
        ldsm4(bf1,     bB + 32);         ldsm4(bf1 + 4, bB + 2304 + 32);
        ldsm4(bf2,     bB + 64);         ldsm4(bf2 + 4, bB + 2304 + 64);
        ldsm4(bf3,     bB + 96);         ldsm4(bf3 + 4, bB + 2304 + 96);

        #pragma unroll
        for (int mt = 0; mt < 2; mt++)
            #pragma unroll
            for (int n = 0; n < 4; n++) {
                const int i0 = (n>>1)*4 + (n&1)*2;
                mma16816(acc[mt][n], Ah0[mt][0],Ah0[mt][1],Ah0[mt][2],Ah0[mt][3], bf0[i0], bf0[i0+1]);
                mma16816(acc[mt][n], Al0[mt][0],Al0[mt][1],Al0[mt][2],Al0[mt][3], bf0[i0], bf0[i0+1]);
                mma16816(acc[mt][n], Ah1[mt][0],Ah1[mt][1],Ah1[mt][2],Ah1[mt][3], bf1[i0], bf1[i0+1]);
                mma16816(acc[mt][n], Al1[mt][0],Al1[mt][1],Al1[mt][2],Al1[mt][3], bf1[i0], bf1[i0+1]);
                mma16816(acc[mt][n], Ah0[mt][0],Ah0[mt][1],Ah0[mt][2],Ah0[mt][3], bf2[i0], bf2[i0+1]);
                mma16816(acc[mt][n], Ah1[mt][0],Ah1[mt][1],Ah1[mt][2],Ah1[mt][3], bf3[i0], bf3[i0+1]);
            }
    }
}

// write per-thread candidates (tanh applied) into transpose buffer S[(py*32+px)*33+cl]
__device__ __forceinline__ void xp_store_cand(
    float* S, float acc[2][4][4], const float* bias, int w, int gid, int tig)
{
    #pragma unroll
    for (int mt = 0; mt < 2; mt++)
        #pragma unroll
        for (int hf = 0; hf < 2; hf++) {
            int px = mt*16 + gid + hf*8;
            #pragma unroll
            for (int n = 0; n < 4; n++)
                #pragma unroll
                for (int q = 0; q < 2; q++) {
                    int cl = n*8 + 2*tig + q;
                    S[(w*32 + px)*33 + cl] = fast_tanh(acc[mt][n][hf*2 + q] + bias[cl]);
                }
        }
}

// ---------------- state kernel (N-split: half=0 -> e channels, 1 -> i) ----------------
__global__ void __launch_bounds__(THREADS, 2)
state_kernel(const float* __restrict__ he, const float* __restrict__ hi,
             float* __restrict__ out)
{
    extern __shared__ char sm[];
    const uint32_t smb = smem_u32(sm);
    const int tid  = threadIdx.x;
    const int w    = tid >> 5;
    const int lane = tid & 31;
    const int gid  = lane >> 2;
    const int tig  = lane & 3;
    const int b    = blockIdx.z >> 1;
    const int half = blockIdx.z & 1;
    const int ty0  = blockIdx.y * 8;
    const int tx0  = blockIdx.x * 32;

    float acc[2][4][4];
    #pragma unroll
    for (int mt = 0; mt < 2; mt++)
        #pragma unroll
        for (int n = 0; n < 4; n++)
            #pragma unroll
            for (int q = 0; q < 4; q++) acc[mt][n][q] = 0.f;

    const int hbase = (w + 1) * 34 + 1;
    const uint32_t laneA0 = smb + A_OFF + (uint32_t)(hbase + (lane & 15)) * RS
                          + (uint32_t)((lane >> 4) << 4);
    const uint32_t laneA1 = laneA0 + 16u*RS;
    const uint32_t laneB  = smb + B_OFF
                          + (uint32_t)((((lane >> 4) & 1)*8 + (lane & 7))) * RS
                          + (uint32_t)(((lane >> 3) & 1) << 4);

    for (int t = 0; t < 3; t++) {
        {
            const char* bsrc = (const char*)g_Bst + (size_t)t*82944 + (size_t)half*41472;
            for (int i = tid; i < B_SZ/16; i += THREADS)
                cp16(smb + B_OFF + (uint32_t)i*16, bsrc + (size_t)i*16);
        }
        stage_A(sm, smb, t, b, ty0, tx0, tid);
        CP_COMMIT();
        CP_WAIT0();
        __syncthreads();

        conv_tap_loop(acc, laneA0, laneA1, laneB);
        __syncthreads();
    }

    // ---- transpose epilogue ----
    float* S = (float*)(sm + XP_OFF);
    xp_store_cand(S, acc, g_bcomb + half*32, w, gid, tig);
    __syncthreads();

    // pass (a): co-major, coalesced global I/O. warp w handles py=w.
    const float* hsrc = (half == 0) ? he : hi;
    float* odst = out + (size_t)(half + 1) * NTOT;
    #pragma unroll 1
    for (int it = 0; it < 8; it++) {
        int cl  = it*4 + (lane >> 3);          // 0..31
        int px0 = (lane & 7) * 4;
        float inv = g_invtau[half*32 + cl];
        size_t gidx = (size_t)b * CHW + (size_t)cl * HW
                    + (size_t)(ty0 + w) * Ww + tx0 + px0;
        float4 h4 = make_float4(0.f, 0.f, 0.f, 0.f);
        if (inv < 1.f) h4 = *(const float4*)(hsrc + gidx);
        float c0 = S[(w*32 + px0    )*33 + cl];
        float c1 = S[(w*32 + px0 + 1)*33 + cl];
        float c2 = S[(w*32 + px0 + 2)*33 + cl];
        float c3 = S[(w*32 + px0 + 3)*33 + cl];
        float4 v = make_float4((1.f-inv)*h4.x + inv*c0, (1.f-inv)*h4.y + inv*c1,
                               (1.f-inv)*h4.z + inv*c2, (1.f-inv)*h4.w + inv*c3);
        *(float4*)(odst + gidx) = v;
        if (half == 0) {
            S[(w*32 + px0    )*33 + cl] = v.x;
            S[(w*32 + px0 + 1)*33 + cl] = v.y;
            S[(w*32 + px0 + 2)*33 + cl] = v.z;
            S[(w*32 + px0 + 3)*33 + cl] = v.w;
        }
    }

    // pass (b): px-major bf16 row emission for h_e_new (e-half only)
    if (half == 0) {
        __syncthreads();
        int py = tid >> 5, px = tid & 31;
        uint32_t hw[16], lw[16];
        #pragma unroll
        for (int k = 0; k < 16; k++) {
            float v0 = S[(py*32 + px)*33 + 2*k];
            float v1 = S[(py*32 + px)*33 + 2*k + 1];
            unsigned short h0, l0, h1, l1;
            bf16split(v0, h0, l0);
            bf16split(v1, h1, l1);
            hw[k] = (uint32_t)h0 | ((uint32_t)h1 << 16);
            lw[k] = (uint32_t)l0 | ((uint32_t)l1 << 16);
        }
        uint4* rp = g_Arows + ((size_t)3 * (Bn*HW)
                  + (size_t)b * HW + (size_t)(ty0 + py) * Ww + tx0 + px) * 8;
        #pragma unroll
        for (int j = 0; j < 4; j++) {
            rp[j]     = make_uint4(hw[4*j], hw[4*j+1], hw[4*j+2], hw[4*j+3]);
            rp[4 + j] = make_uint4(lw[4*j], lw[4*j+1], lw[4*j+2], lw[4*j+3]);
        }
    }
}

// ---------------- out kernel ----------------
__global__ void __launch_bounds__(THREADS, 2)
out_kernel(float* __restrict__ out)
{
    extern __shared__ char sm[];
    const uint32_t smb = smem_u32(sm);
    const int tid  = threadIdx.x;
    const int w    = tid >> 5;
    const int lane = tid & 31;
    const int gid  = lane >> 2;
    const int tig  = lane & 3;
    const int b    = blockIdx.z;
    const int ty0  = blockIdx.y * 8;
    const int tx0  = blockIdx.x * 32;

    float acc[2][4][4];
    #pragma unroll
    for (int mt = 0; mt < 2; mt++)
        #pragma unroll
        for (int n = 0; n < 4; n++)
            #pragma unroll
            for (int q = 0; q < 4; q++) acc[mt][n][q] = 0.f;

    const int hbase = (w + 1) * 34 + 1;
    const uint32_t laneA0 = smb + A_OFF + (uint32_t)(hbase + (lane & 15)) * RS
                          + (uint32_t)((lane >> 4) << 4);
    const uint32_t laneA1 = laneA0 + 16u*RS;
    const uint32_t laneB  = smb + B_OFF
                          + (uint32_t)((((lane >> 4) & 1)*8 + (lane & 7))) * RS
                          + (uint32_t)(((lane >> 3) & 1) << 4);

    {
        const char* bsrc = (const char*)g_Bout;
        for (int i = tid; i < B_SZ/16; i += THREADS)
            cp16(smb + B_OFF + (uint32_t)i*16, bsrc + (size_t)i*16);
    }
    stage_A(sm, smb, 3, b, ty0, tx0, tid);
    CP_COMMIT();
    CP_WAIT0();
    __syncthreads();

    conv_tap_loop(acc, laneA0, laneA1, laneB);
    __syncthreads();

    // transpose epilogue: tanh in SMEM, coalesced stores
    float* S = (float*)(sm + XP_OFF);
    xp_store_cand(S, acc, g_bout, w, gid, tig);
    __syncthreads();

    #pragma unroll 1
    for (int it = 0; it < 8; it++) {
        int cl  = it*4 + (lane >> 3);
        int px0 = (lane & 7) * 4;
        size_t gidx = (size_t)b * CHW + (size_t)cl * HW
                    + (size_t)(ty0 + w) * Ww + tx0 + px0;
        float4 v = make_float4(S[(w*32 + px0    )*33 + cl],
                               S[(w*32 + px0 + 1)*33 + cl],
                               S[(w*32 + px0 + 2)*33 + cl],
                               S[(w*32 + px0 + 3)*33 + cl]);
        *(float4*)(out + gidx) = v;
    }
}

extern "C" void kernel_launch(void* const* d_in, const int* in_sizes, int n_in,
                              void* d_out, int out_size)
{
    (void)in_sizes; (void)n_in; (void)out_size;
    const float* x  = (const float*)d_in[0];
    const float* he = (const float*)d_in[1];
    const float* hi = (const float*)d_in[2];
    float* out = (float*)d_out;

    cudaFuncSetAttribute(state_kernel, cudaFuncAttributeMaxDynamicSharedMemorySize, SMEM_T);
    cudaFuncSetAttribute(out_kernel,   cudaFuncAttributeMaxDynamicSharedMemorySize, SMEM_T);

    prep_kernel<<<252, 256>>>(
        (const float*)d_in[3],  (const float*)d_in[4],
        (const float*)d_in[5],  (const float*)d_in[6],
        (const float*)d_in[7],  (const float*)d_in[8],
        (const float*)d_in[9],  (const float*)d_in[10],
        (const float*)d_in[11], (const float*)d_in[12],
        (const float*)d_in[13], (const float*)d_in[14],
        (const float*)d_in[15], (const float*)d_in[16],
        (const float*)d_in[17], (const float*)d_in[18]);

    convert_kernel<<<(3*Bn*HW)/256, 256>>>(x, he, hi);

    dim3 gs(4, 16, Bn*2);   // x-tiles, y-tiles, batch x co-half
    state_kernel<<<gs, THREADS, SMEM_T>>>(he, hi, out);
    dim3 go(4, 16, Bn);
    out_kernel<<<go, THREADS, SMEM_T>>>(out);
}

// round 11
// speedup vs baseline: 1.0063x; 1.0063x over previous
#include <cuda_runtime.h>
#include <math.h>
#include <stdint.h>

#define Bn 16
#define Cc 32
#define Hh 128
#define Ww 128
#define HW (Hh*Ww)
#define CHW (Cc*HW)
#define NTOT (Bn*CHW)

// block tile: 8 out rows x 32 out cols = 256 px; halo 10x34 = 340 A rows
#define THREADS 256
#define NROWS 340

#define RS     144                    // padded SMEM row stride (128 data + 16)
#define A_OFF  0
#define A_SZ   (NROWS*RS)             // 48960 bytes; A is the only SMEM user

// global A-row images: [t(4)][b*HW + pix] rows of 128B ([hi 32ci | lo 32ci] bf16)
__device__ uint4 g_Arows[(size_t)4*Bn*HW*8];

// B fragment tables (register-image order; uint4 per (lane, s,p) group)
// state: [t(3)][half(2)][tap(9)][sp(8)][lane(32)]  -> 13824 uint4
// out:   [tap(9)][sp(8)][lane(32)]                 -> 2304 uint4
#define STFRAG (3*2*9*8*32)
#define OUTFRAG (9*8*32)
__device__ __align__(16) uint4 g_BfragSt[STFRAG];
__device__ __align__(16) uint4 g_BfragOut[OUTFRAG];
__device__ float g_bcomb[64];
__device__ float g_bout[32];
__device__ float g_invtau[64];

// ---------------- helpers ----------------
__device__ __forceinline__ uint32_t smem_u32(const void* p) {
    uint32_t a;
    asm("{ .reg .u64 t; cvta.to.shared.u64 t, %1; cvt.u32.u64 %0, t; }" : "=r"(a) : "l"(p));
    return a;
}
__device__ __forceinline__ void bf16split(float v, unsigned short& h, unsigned short& l) {
    asm("cvt.rn.bf16.f32 %0, %1;" : "=h"(h) : "f"(v));
    float hf;
    asm("cvt.f32.bf16 %0, %1;" : "=f"(hf) : "h"(h));
    asm("cvt.rn.bf16.f32 %0, %1;" : "=h"(l) : "f"(v - hf));
}
__device__ __forceinline__ float fast_tanh(float x) {
    float e, r;
    asm("ex2.approx.f32 %0, %1;" : "=f"(e) : "f"(x * 2.8853900817779268f));
    asm("rcp.approx.f32 %0, %1;" : "=f"(r) : "f"(e + 1.f));
    return fmaf(-2.f, r, 1.f);
}
__device__ __forceinline__ void mma16816(float* c,
    uint32_t a0, uint32_t a1, uint32_t a2, uint32_t a3, uint32_t b0, uint32_t b1)
{
    asm volatile(
        "mma.sync.aligned.m16n8k16.row.col.f32.bf16.bf16.f32 "
        "{%0,%1,%2,%3}, {%4,%5,%6,%7}, {%8,%9}, {%0,%1,%2,%3};"
        : "+f"(c[0]), "+f"(c[1]), "+f"(c[2]), "+f"(c[3])
        : "r"(a0), "r"(a1), "r"(a2), "r"(a3), "r"(b0), "r"(b1));
}
__device__ __forceinline__ void ldsm4(uint32_t* r, uint32_t addr) {
    asm volatile("ldmatrix.sync.aligned.m8n8.x4.shared.b16 {%0,%1,%2,%3}, [%4];"
        : "=r"(r[0]), "=r"(r[1]), "=r"(r[2]), "=r"(r[3]) : "r"(addr));
}
__device__ __forceinline__ void cp16(uint32_t smdst, const void* gsrc) {
    asm volatile("cp.async.cg.shared.global [%0], [%1], 16;" :: "r"(smdst), "l"(gsrc));
}
#define CP_COMMIT() asm volatile("cp.async.commit_group;" ::: "memory")
#define CP_WAIT0()  asm volatile("cp.async.wait_group 0;" ::: "memory")

// ---------------- prep: Dale fold + bf16 split, emitted in FRAGMENT order ----------------
// fragment convention (verified by working ldmatrix kernels):
//   reg j of lane t in (s,p) group = elements (kk, kk+1) of B-row co:
//   co_local = p*16 + ((j>>1)<<3) + (t>>2)
//   kk       = s*16 + ((j&1)<<3) + ((t&3)<<1)   over row [hi(0..31) | lo(32..63)]
__global__ void prep_kernel(
    const float* __restrict__ W_in_e, const float* __restrict__ b_in_e,
    const float* __restrict__ W_in_i, const float* __restrict__ b_in_i,
    const float* __restrict__ W_e_e,  const float* __restrict__ b_e_e,
    const float* __restrict__ W_e_i,  const float* __restrict__ b_e_i,
    const float* __restrict__ W_e_out,const float* __restrict__ b_e_out,
    const float* __restrict__ W_i_e,  const float* __restrict__ b_i_e,
    const float* __restrict__ W_i_i,  const float* __restrict__ b_i_i,
    const float* __restrict__ tau_e,  const float* __restrict__ tau_i)
{
    int fid = blockIdx.x * 256 + threadIdx.x;
    if (fid < STFRAG) {
        int lane = fid & 31;
        int q    = fid >> 5;
        int p    = q & 1;  q >>= 1;
        int s    = q & 3;  q >>= 2;
        int tap  = q % 9;  q /= 9;
        int half = q & 1;
        int t    = q >> 1;
        uint32_t comp[4];
        #pragma unroll
        for (int j = 0; j < 4; j++) {
            int co_l = p*16 + ((j>>1)<<3) + (lane>>2);
            int kk   = s*16 + ((j&1)<<3) + ((lane&3)<<1);
            int plane = kk >> 5;         // 0=hi, 1=lo
            int ci    = kk & 31;
            unsigned short v[2];
            #pragma unroll
            for (int e = 0; e < 2; e++) {
                int src = co_l * 288 + (ci + e) * 9 + tap;   // OIHW
                float w;
                if (t == 0)      w = (half == 0) ? W_in_e[src] : W_in_i[src];
                else if (t == 1) w = fmaxf((half == 0) ? W_e_e[src] : W_e_i[src], 0.f);
                else             w = -fmaxf((half == 0) ? W_i_e[src] : W_i_i[src], 0.f);
                unsigned short h, l;
                bf16split(w, h, l);
                v[e] = plane ? l : h;
            }
            comp[j] = (uint32_t)v[0] | ((uint32_t)v[1] << 16);
        }
        g_BfragSt[fid] = make_uint4(comp[0], comp[1], comp[2], comp[3]);
    } else if (fid < STFRAG + OUTFRAG) {
        int f2   = fid - STFRAG;
        int lane = f2 & 31;
        int q    = f2 >> 5;
        int p    = q & 1;  q >>= 1;
        int s    = q & 3;  q >>= 2;
        int tap  = q;                      // 0..8
        uint32_t comp[4];
        #pragma unroll
        for (int j = 0; j < 4; j++) {
            int co_l = p*16 + ((j>>1)<<3) + (lane>>2);
            int kk   = s*16 + ((j&1)<<3) + ((lane&3)<<1);
            int plane = kk >> 5;
            int ci    = kk & 31;
            unsigned short v[2];
            #pragma unroll
            for (int e = 0; e < 2; e++) {
                float w = fmaxf(W_e_out[co_l*288 + (ci + e)*9 + tap], 0.f);
                unsigned short h, l;
                bf16split(w, h, l);
                v[e] = plane ? l : h;
            }
            comp[j] = (uint32_t)v[0] | ((uint32_t)v[1] << 16);
        }
        g_BfragOut[f2] = make_uint4(comp[0], comp[1], comp[2], comp[3]);
    }
    if (blockIdx.x == 0 && threadIdx.x < 64) {
        int co = threadIdx.x;
        if (co < 32) {
            g_bcomb[co]  = b_in_e[co] + fmaxf(b_e_e[co], 0.f) - fmaxf(b_i_e[co], 0.f);
            g_invtau[co] = 1.f / fmaxf(tau_e[co], 1.f);
            g_bout[co]   = fmaxf(b_e_out[co], 0.f);
        } else {
            int c = co - 32;
            g_bcomb[co]  = b_in_i[c] + fmaxf(b_e_i[c], 0.f) - fmaxf(b_i_i[c], 0.f);
            g_invtau[co] = 1.f / fmaxf(tau_i[c], 1.f);
        }
    }
}

// ---------------- convert: NCHW fp32 -> per-pixel 128B bf16 hi/lo rows ----------------
__global__ void __launch_bounds__(256)
convert_kernel(const float* __restrict__ x, const float* __restrict__ he,
               const float* __restrict__ hi)
{
    int gidx = blockIdx.x * 256 + threadIdx.x;
    int t = gidx / (Bn*HW);
    int p = gidx - t * (Bn*HW);
    int b = p / HW;
    int pix = p - b * HW;
    const float* src = (t == 0 ? x : (t == 1 ? he : hi)) + (size_t)b * CHW + pix;
    uint4* dst = g_Arows + ((size_t)t * (Bn*HW) + p) * 8;

    uint32_t hw[16], lw[16];
    #pragma unroll
    for (int k = 0; k < 16; k++) {
        float v0 = src[(size_t)(2*k)   * HW];
        float v1 = src[(size_t)(2*k+1) * HW];
        unsigned short h0, l0, h1, l1;
        bf16split(v0, h0, l0);
        bf16split(v1, h1, l1);
        hw[k] = (uint32_t)h0 | ((uint32_t)h1 << 16);
        lw[k] = (uint32_t)l0 | ((uint32_t)l1 << 16);
    }
    #pragma unroll
    for (int j = 0; j < 4; j++) {
        dst[j]     = make_uint4(hw[4*j], hw[4*j+1], hw[4*j+2], hw[4*j+3]);
        dst[4 + j] = make_uint4(lw[4*j], lw[4*j+1], lw[4*j+2], lw[4*j+3]);
    }
}

// ---------------- A tile staging: division-free, hoisted predicates ----------------
// thread -> (chunk c = tid&7, column col = tid>>3). Primary rx=col; threads with
// col<2 also handle rx=col+32. Loop over 10 halo rows with constant strides.
__device__ __forceinline__ void stage_A(char* sm, uint32_t smb,
                                        int t, int b, int ty0, int tx0, int tid)
{
    const char* gb = (const char*)g_Arows + ((size_t)t * (Bn*HW) + (size_t)b * HW) * 128;
    const int c   = tid & 7;
    const int col = tid >> 3;

    const int gx1  = tx0 + col - 1;
    const bool okx1 = ((unsigned)gx1 < 128u);
    uint32_t dst1 = smb + A_OFF + (uint32_t)col * RS + (uint32_t)c * 16;
    const char* src1 = gb + ((size_t)(ty0 - 1) * Ww + gx1) * 128 + c * 16;

    const bool has2 = (col < 2);
    const int gx2  = tx0 + col + 31;
    const bool okx2 = has2 && ((unsigned)gx2 < 128u);
    uint32_t dst2 = smb + A_OFF + (uint32_t)(col + 32) * RS + (uint32_t)c * 16;
    const char* src2 = gb + ((size_t)(ty0 - 1) * Ww + gx2) * 128 + c * 16;

    #pragma unroll
    for (int ry = 0; ry < 10; ry++) {
        const int gy = ty0 + ry - 1;
        const bool oky = ((unsigned)gy < 128u);
        if (oky && okx1) cp16(dst1, src1);
        else             *(uint4*)(sm + (dst1 - smb)) = make_uint4(0,0,0,0);
        if (has2) {
            if (oky && okx2) cp16(dst2, src2);
            else             *(uint4*)(sm + (dst2 - smb)) = make_uint4(0,0,0,0);
        }
        dst1 += 34u * RS;  src1 += (size_t)Ww * 128;
        dst2 += 34u * RS;  src2 += (size_t)Ww * 128;
    }
}

// ---------------- mainloop: A via ldmatrix, B via coalesced LDG.128 frag table ----------------
__device__ __forceinline__ void conv_tap_loop(
    float acc[2][4][4], const uint32_t laneA0, const uint32_t laneA1,
    const uint4* __restrict__ Bp)   // points at [tap=0][sp=0][lane]
{
    #pragma unroll 1
    for (int tap = 0; tap < 9; tap++) {
        const int soff = ((tap/3) - 1) * (34*RS) + ((tap % 3) - 1) * RS;
        const uint32_t aA0 = laneA0 + soff;
        const uint32_t aA1 = laneA1 + soff;
        const uint4* bp = Bp + (size_t)tap * 256;

        // B fragments: 8 coalesced LDG.128 (L1-resident table)
        uint32_t bf[4][8];
        #pragma unroll
        for (int sp = 0; sp < 8; sp++) {
            uint4 qv = bp[(size_t)sp * 32];
            const int s = sp >> 1, p = sp & 1;
            bf[s][p*4+0] = qv.x; bf[s][p*4+1] = qv.y;
            bf[s][p*4+2] = qv.z; bf[s][p*4+3] = qv.w;
        }

        // A fragments: 8 ldmatrix.x4
        uint32_t Ah0[2][4], Ah1[2][4], Al0[2][4], Al1[2][4];
        ldsm4(Ah0[0], aA0 + 0);  ldsm4(Ah1[0], aA0 + 32);
        ldsm4(Al0[0], aA0 + 64); ldsm4(Al1[0], aA0 + 96);
        ldsm4(Ah0[1], aA1 + 0);  ldsm4(Ah1[1], aA1 + 32);
        ldsm4(Al0[1], aA1 + 64); ldsm4(Al1[1], aA1 + 96);

        #pragma unroll
        for (int mt = 0; mt < 2; mt++)
            #pragma unroll
            for (int n = 0; n < 4; n++) {
                const int i0 = (n>>1)*4 + (n&1)*2;
                mma16816(acc[mt][n], Ah0[mt][0],Ah0[mt][1],Ah0[mt][2],Ah0[mt][3], bf[0][i0], bf[0][i0+1]);
                mma16816(acc[mt][n], Al0[mt][0],Al0[mt][1],Al0[mt][2],Al0[mt][3], bf[0][i0], bf[0][i0+1]);
                mma16816(acc[mt][n], Ah1[mt][0],Ah1[mt][1],Ah1[mt][2],Ah1[mt][3], bf[1][i0], bf[1][i0+1]);
                mma16816(acc[mt][n], Al1[mt][0],Al1[mt][1],Al1[mt][2],Al1[mt][3], bf[1][i0], bf[1][i0+1]);
                mma16816(acc[mt][n], Ah0[mt][0],Ah0[mt][1],Ah0[mt][2],Ah0[mt][3], bf[2][i0], bf[2][i0+1]);
                mma16816(acc[mt][n], Ah1[mt][0],Ah1[mt][1],Ah1[mt][2],Ah1[mt][3], bf[3][i0], bf[3][i0+1]);
            }
    }
}

// ---------------- state kernel (N-split: half=0 -> e channels, 1 -> i) ----------------
__global__ void __launch_bounds__(THREADS, 2)
state_kernel(const float* __restrict__ he, const float* __restrict__ hi,
             float* __restrict__ out)
{
    extern __shared__ char sm[];
    const uint32_t smb = smem_u32(sm);
    const int tid  = threadIdx.x;
    const int w    = tid >> 5;
    const int lane = tid & 31;
    const int gid  = lane >> 2;
    const int tig  = lane & 3;
    const int b    = blockIdx.z >> 1;
    const int half = blockIdx.z & 1;
    const int ty0  = blockIdx.y * 8;
    const int tx0  = blockIdx.x * 32;

    float acc[2][4][4];
    #pragma unroll
    for (int mt = 0; mt < 2; mt++)
        #pragma unroll
        for (int n = 0; n < 4; n++)
            #pragma unroll
            for (int q = 0; q < 4; q++) acc[mt][n][q] = 0.f;

    const int hbase = (w + 1) * 34 + 1;
    const uint32_t laneA0 = smb + A_OFF + (uint32_t)(hbase + (lane & 15)) * RS
                          + (uint32_t)((lane >> 4) << 4);
    const uint32_t laneA1 = laneA0 + 16u*RS;

    for (int t = 0; t < 3; t++) {
        stage_A(sm, smb, t, b, ty0, tx0, tid);
        CP_COMMIT();
        CP_WAIT0();
        __syncthreads();

        const uint4* Bp = g_BfragSt + ((size_t)(t*2 + half) * 9) * 256 + lane;
        conv_tap_loop(acc, laneA0, laneA1, Bp);
        __syncthreads();
    }

    // epilogue (round-9 direct form) + h_e_new bf16 row emission
    uint32_t* rowbase = (uint32_t*)(g_Arows + (size_t)3 * (Bn*HW) * 8);
    #pragma unroll
    for (int mt = 0; mt < 2; mt++) {
        #pragma unroll
        for (int hf = 0; hf < 2; hf++) {
            int px_local = mt*16 + gid + hf*8;
            int py = ty0 + w;
            int px = tx0 + px_local;
            size_t pidx = (size_t)b * CHW + (size_t)py * Ww + px;
            uint32_t* rp = rowbase + ((size_t)b * HW + (size_t)py * Ww + px) * 32;
            #pragma unroll
            for (int n = 0; n < 4; n++) {
                int cl = n*8 + 2*tig;
                int co = half*32 + cl;
                float a0 = acc[mt][n][hf*2]     + g_bcomb[co];
                float a1 = acc[mt][n][hf*2 + 1] + g_bcomb[co+1];
                float i0 = g_invtau[co], i1 = g_invtau[co+1];
                float c0 = fast_tanh(a0), c1 = fast_tanh(a1);
                if (half == 0) {
                    float h0 = (i0 < 1.f) ? he[pidx + (size_t)cl * HW]     : 0.f;
                    float h1 = (i1 < 1.f) ? he[pidx + (size_t)(cl+1) * HW] : 0.f;
                    float v0 = (1.f - i0)*h0 + i0*c0;
                    float v1 = (1.f - i1)*h1 + i1*c1;
                    out[(size_t)NTOT + pidx + (size_t)cl * HW]     = v0;
                    out[(size_t)NTOT + pidx + (size_t)(cl+1) * HW] = v1;
                    unsigned short h0b, l0b, h1b, l1b;
                    bf16split(v0, h0b, l0b);
                    bf16split(v1, h1b, l1b);
                    int widx = cl >> 1;
                    rp[widx]      = (uint32_t)h0b | ((uint32_t)h1b << 16);
                    rp[16 + widx] = (uint32_t)l0b | ((uint32_t)l1b << 16);
                } else {
                    float h0 = (i0 < 1.f) ? hi[pidx + (size_t)cl * HW]     : 0.f;
                    float h1 = (i1 < 1.f) ? hi[pidx + (size_t)(cl+1) * HW] : 0.f;
                    out[(size_t)2*NTOT + pidx + (size_t)cl * HW]     = (1.f - i0)*h0 + i0*c0;
                    out[(size_t)2*NTOT + pidx + (size_t)(cl+1) * HW] = (1.f - i1)*h1 + i1*c1;
                }
            }
        }
    }
}

// ---------------- out kernel ----------------
__global__ void __launch_bounds__(THREADS, 2)
out_kernel(float* __restrict__ out)
{
    extern __shared__ char sm[];
    const uint32_t smb = smem_u32(sm);
    const int tid  = threadIdx.x;
    const int w    = tid >> 5;
    const int lane = tid & 31;
    const int gid  = lane >> 2;
    const int tig  = lane & 3;
    const int b    = blockIdx.z;
    const int ty0  = blockIdx.y * 8;
    const int tx0  = blockIdx.x * 32;

    float acc[2][4][4];
    #pragma unroll
    for (int mt = 0; mt < 2; mt++)
        #pragma unroll
        for (int n = 0; n < 4; n++)
            #pragma unroll
            for (int q = 0; q < 4; q++) acc[mt][n][q] = 0.f;

    const int hbase = (w + 1) * 34 + 1;
    const uint32_t laneA0 = smb + A_OFF + (uint32_t)(hbase + (lane & 15)) * RS
                          + (uint32_t)((lane >> 4) << 4);
    const uint32_t laneA1 = laneA0 + 16u*RS;

    stage_A(sm, smb, 3, b, ty0, tx0, tid);
    CP_COMMIT();
    CP_WAIT0();
    __syncthreads();

    const uint4* Bp = g_BfragOut + lane;
    conv_tap_loop(acc, laneA0, laneA1, Bp);

    #pragma unroll
    for (int mt = 0; mt < 2; mt++) {
        #pragma unroll
        for (int hf = 0; hf < 2; hf++) {
            int px_local = mt*16 + gid + hf*8;
            int py = ty0 + w;
            int px = tx0 + px_local;
            size_t pidx = (size_t)b * CHW + (size_t)py * Ww + px;
            #pragma unroll
            for (int n = 0; n < 4; n++) {
                #pragma unroll
                for (int q = 0; q < 2; q++) {
                    int co  = n*8 + 2*tig + q;
                    float v = acc[mt][n][hf*2 + q] + g_bout[co];
                    out[pidx + (size_t)co * HW] = fast_tanh(v);
                }
            }
        }
    }
}

extern "C" void kernel_launch(void* const* d_in, const int* in_sizes, int n_in,
                              void* d_out, int out_size)
{
    (void)in_sizes; (void)n_in; (void)out_size;
    const float* x  = (const float*)d_in[0];
    const float* he = (const float*)d_in[1];
    const float* hi = (const float*)d_in[2];
    float* out = (float*)d_out;

    cudaFuncSetAttribute(state_kernel, cudaFuncAttributeMaxDynamicSharedMemorySize, A_SZ);
    cudaFuncSetAttribute(out_kernel,   cudaFuncAttributeMaxDynamicSharedMemorySize, A_SZ);

    prep_kernel<<<63, 256>>>(
        (const float*)d_in[3],  (const float*)d_in[4],
        (const float*)d_in[5],  (const float*)d_in[6],
        (const float*)d_in[7],  (const float*)d_in[8],
        (const float*)d_in[9],  (const float*)d_in[10],
        (const float*)d_in[11], (const float*)d_in[12],
        (const float*)d_in[13], (const float*)d_in[14],
        (const float*)d_in[15], (const float*)d_in[16],
        (const float*)d_in[17], (const float*)d_in[18]);

    convert_kernel<<<(3*Bn*HW)/256, 256>>>(x, he, hi);

    dim3 gs(4, 16, Bn*2);   // x-tiles, y-tiles, batch x co-half
    state_kernel<<<gs, THREADS, A_SZ>>>(he, hi, out);
    dim3 go(4, 16, Bn);
    out_kernel<<<go, THREADS, A_SZ>>>(out);
}

// round 12
// speedup vs baseline: 1.0097x; 1.0034x over previous
#include <cuda_runtime.h>
#include <math.h>
#include <stdint.h>

#define Bn 16
#define Cc 32
#define Hh 128
#define Ww 128
#define HW (Hh*Ww)
#define CHW (Cc*HW)
#define NTOT (Bn*CHW)

// block tile: 8 out rows x 32 out cols = 256 px; halo 10x34 = 340 A rows
#define THREADS 256
#define NROWS 340

#define RS     144                    // padded SMEM row stride (128 data + 16)
#define A_SZ   (NROWS*RS)             // 48960 bytes per buffer
#define SMEM_T (2*A_SZ)               // 97920: double-buffered A (2 blocks/SM)

// global A-row images: [t(4)][b*HW + pix] rows of 128B ([hi 32ci | lo 32ci] bf16)
__device__ uint4 g_Arows[(size_t)4*Bn*HW*8];

// B fragment tables (register-image order; uint4 per (lane, s,p) group)
#define STFRAG (3*2*9*8*32)
#define OUTFRAG (9*8*32)
__device__ __align__(16) uint4 g_BfragSt[STFRAG];
__device__ __align__(16) uint4 g_BfragOut[OUTFRAG];
__device__ float g_bcomb[64];
__device__ float g_bout[32];
__device__ float g_invtau[64];

// ---------------- helpers ----------------
__device__ __forceinline__ uint32_t smem_u32(const void* p) {
    uint32_t a;
    asm("{ .reg .u64 t; cvta.to.shared.u64 t, %1; cvt.u32.u64 %0, t; }" : "=r"(a) : "l"(p));
    return a;
}
__device__ __forceinline__ void bf16split(float v, unsigned short& h, unsigned short& l) {
    asm("cvt.rn.bf16.f32 %0, %1;" : "=h"(h) : "f"(v));
    float hf;
    asm("cvt.f32.bf16 %0, %1;" : "=f"(hf) : "h"(h));
    asm("cvt.rn.bf16.f32 %0, %1;" : "=h"(l) : "f"(v - hf));
}
__device__ __forceinline__ float fast_tanh(float x) {
    float e, r;
    asm("ex2.approx.f32 %0, %1;" : "=f"(e) : "f"(x * 2.8853900817779268f));
    asm("rcp.approx.f32 %0, %1;" : "=f"(r) : "f"(e + 1.f));
    return fmaf(-2.f, r, 1.f);
}
__device__ __forceinline__ void mma16816(float* c,
    uint32_t a0, uint32_t a1, uint32_t a2, uint32_t a3, uint32_t b0, uint32_t b1)
{
    asm volatile(
        "mma.sync.aligned.m16n8k16.row.col.f32.bf16.bf16.f32 "
        "{%0,%1,%2,%3}, {%4,%5,%6,%7}, {%8,%9}, {%0,%1,%2,%3};"
        : "+f"(c[0]), "+f"(c[1]), "+f"(c[2]), "+f"(c[3])
        : "r"(a0), "r"(a1), "r"(a2), "r"(a3), "r"(b0), "r"(b1));
}
__device__ __forceinline__ void ldsm4(uint32_t* r, uint32_t addr) {
    asm volatile("ldmatrix.sync.aligned.m8n8.x4.shared.b16 {%0,%1,%2,%3}, [%4];"
        : "=r"(r[0]), "=r"(r[1]), "=r"(r[2]), "=r"(r[3]) : "r"(addr));
}
__device__ __forceinline__ void cp16(uint32_t smdst, const void* gsrc) {
    asm volatile("cp.async.cg.shared.global [%0], [%1], 16;" :: "r"(smdst), "l"(gsrc));
}
#define CP_COMMIT() asm volatile("cp.async.commit_group;" ::: "memory")
#define CP_WAIT0()  asm volatile("cp.async.wait_group 0;" ::: "memory")
#define CP_WAIT1()  asm volatile("cp.async.wait_group 1;" ::: "memory")

// ---------------- prep: Dale fold + bf16 split, emitted in FRAGMENT order ----------------
__global__ void prep_kernel(
    const float* __restrict__ W_in_e, const float* __restrict__ b_in_e,
    const float* __restrict__ W_in_i, const float* __restrict__ b_in_i,
    const float* __restrict__ W_e_e,  const float* __restrict__ b_e_e,
    const float* __restrict__ W_e_i,  const float* __restrict__ b_e_i,
    const float* __restrict__ W_e_out,const float* __restrict__ b_e_out,
    const float* __restrict__ W_i_e,  const float* __restrict__ b_i_e,
    const float* __restrict__ W_i_i,  const float* __restrict__ b_i_i,
    const float* __restrict__ tau_e,  const float* __restrict__ tau_i)
{
    int fid = blockIdx.x * 256 + threadIdx.x;
    if (fid < STFRAG) {
        int lane = fid & 31;
        int q    = fid >> 5;
        int p    = q & 1;  q >>= 1;
        int s    = q & 3;  q >>= 2;
        int tap  = q % 9;  q /= 9;
        int half = q & 1;
        int t    = q >> 1;
        uint32_t comp[4];
        #pragma unroll
        for (int j = 0; j < 4; j++) {
            int co_l = p*16 + ((j>>1)<<3) + (lane>>2);
            int kk   = s*16 + ((j&1)<<3) + ((lane&3)<<1);
            int plane = kk >> 5;         // 0=hi, 1=lo
            int ci    = kk & 31;
            unsigned short v[2];
            #pragma unroll
            for (int e = 0; e < 2; e++) {
                int src = co_l * 288 + (ci + e) * 9 + tap;   // OIHW
                float w;
                if (t == 0)      w = (half == 0) ? W_in_e[src] : W_in_i[src];
                else if (t == 1) w = fmaxf((half == 0) ? W_e_e[src] : W_e_i[src], 0.f);
                else             w = -fmaxf((half == 0) ? W_i_e[src] : W_i_i[src], 0.f);
                unsigned short h, l;
                bf16split(w, h, l);
                v[e] = plane ? l : h;
            }
            comp[j] = (uint32_t)v[0] | ((uint32_t)v[1] << 16);
        }
        g_BfragSt[fid] = make_uint4(comp[0], comp[1], comp[2], comp[3]);
    } else if (fid < STFRAG + OUTFRAG) {
        int f2   = fid - STFRAG;
        int lane = f2 & 31;
        int q    = f2 >> 5;
        int p    = q & 1;  q >>= 1;
        int s    = q & 3;  q >>= 2;
        int tap  = q;
        uint32_t comp[4];
        #pragma unroll
        for (int j = 0; j < 4; j++) {
            int co_l = p*16 + ((j>>1)<<3) + (lane>>2);
            int kk   = s*16 + ((j&1)<<3) + ((lane&3)<<1);
            int plane = kk >> 5;
            int ci    = kk & 31;
            unsigned short v[2];
            #pragma unroll
            for (int e = 0; e < 2; e++) {
                float w = fmaxf(W_e_out[co_l*288 + (ci + e)*9 + tap], 0.f);
                unsigned short h, l;
                bf16split(w, h, l);
                v[e] = plane ? l : h;
            }
            comp[j] = (uint32_t)v[0] | ((uint32_t)v[1] << 16);
        }
        g_BfragOut[f2] = make_uint4(comp[0], comp[1], comp[2], comp[3]);
    }
    if (blockIdx.x == 0 && threadIdx.x < 64) {
        int co = threadIdx.x;
        if (co < 32) {
            g_bcomb[co]  = b_in_e[co] + fmaxf(b_e_e[co], 0.f) - fmaxf(b_i_e[co], 0.f);
            g_invtau[co] = 1.f / fmaxf(tau_e[co], 1.f);
            g_bout[co]   = fmaxf(b_e_out[co], 0.f);
        } else {
            int c = co - 32;
            g_bcomb[co]  = b_in_i[c] + fmaxf(b_e_i[c], 0.f) - fmaxf(b_i_i[c], 0.f);
            g_invtau[co] = 1.f / fmaxf(tau_i[c], 1.f);
        }
    }
}

// ---------------- convert: NCHW fp32 -> per-pixel 128B bf16 hi/lo rows ----------------
__global__ void __launch_bounds__(256)
convert_kernel(const float* __restrict__ x, const float* __restrict__ he,
               const float* __restrict__ hi)
{
    int gidx = blockIdx.x * 256 + threadIdx.x;
    int t = gidx / (Bn*HW);
    int p = gidx - t * (Bn*HW);
    int b = p / HW;
    int pix = p - b * HW;
    const float* src = (t == 0 ? x : (t == 1 ? he : hi)) + (size_t)b * CHW + pix;
    uint4* dst = g_Arows + ((size_t)t * (Bn*HW) + p) * 8;

    uint32_t hw[16], lw[16];
    #pragma unroll
    for (int k = 0; k < 16; k++) {
        float v0 = src[(size_t)(2*k)   * HW];
        float v1 = src[(size_t)(2*k+1) * HW];
        unsigned short h0, l0, h1, l1;
        bf16split(v0, h0, l0);
        bf16split(v1, h1, l1);
        hw[k] = (uint32_t)h0 | ((uint32_t)h1 << 16);
        lw[k] = (uint32_t)l0 | ((uint32_t)l1 << 16);
    }
    #pragma unroll
    for (int j = 0; j < 4; j++) {
        dst[j]     = make_uint4(hw[4*j], hw[4*j+1], hw[4*j+2], hw[4*j+3]);
        dst[4 + j] = make_uint4(lw[4*j], lw[4*j+1], lw[4*j+2], lw[4*j+3]);
    }
}

// ---------------- A tile staging: division-free, hoisted predicates ----------------
__device__ __forceinline__ void stage_A(char* sm, uint32_t smb, uint32_t a_off,
                                        int t, int b, int ty0, int tx0, int tid)
{
    const char* gb = (const char*)g_Arows + ((size_t)t * (Bn*HW) + (size_t)b * HW) * 128;
    const int c   = tid & 7;
    const int col = tid >> 3;

    const int gx1  = tx0 + col - 1;
    const bool okx1 = ((unsigned)gx1 < 128u);
    uint32_t dst1 = smb + a_off + (uint32_t)col * RS + (uint32_t)c * 16;
    const char* src1 = gb + ((size_t)(ty0 - 1) * Ww + gx1) * 128 + c * 16;

    const bool has2 = (col < 2);
    const int gx2  = tx0 + col + 31;
    const bool okx2 = has2 && ((unsigned)gx2 < 128u);
    uint32_t dst2 = smb + a_off + (uint32_t)(col + 32) * RS + (uint32_t)c * 16;
    const char* src2 = gb + ((size_t)(ty0 - 1) * Ww + gx2) * 128 + c * 16;

    #pragma unroll
    for (int ry = 0; ry < 10; ry++) {
        const int gy = ty0 + ry - 1;
        const bool oky = ((unsigned)gy < 128u);
        if (oky && okx1) cp16(dst1, src1);
        else             *(uint4*)(sm + (dst1 - smb)) = make_uint4(0,0,0,0);
        if (has2) {
            if (oky && okx2) cp16(dst2, src2);
            else             *(uint4*)(sm + (dst2 - smb)) = make_uint4(0,0,0,0);
        }
        dst1 += 34u * RS;  src1 += (size_t)Ww * 128;
        dst2 += 34u * RS;  src2 += (size_t)Ww * 128;
    }
}

// ---------------- mainloop: A via ldmatrix, B via coalesced LDG.128 frag table ----------------
__device__ __forceinline__ void conv_tap_loop(
    float acc[2][4][4], const uint32_t laneA0, const uint32_t laneA1,
    const uint4* __restrict__ Bp)
{
    #pragma unroll 1
    for (int tap = 0; tap < 9; tap++) {
        const int soff = ((tap/3) - 1) * (34*RS) + ((tap % 3) - 1) * RS;
        const uint32_t aA0 = laneA0 + soff;
        const uint32_t aA1 = laneA1 + soff;
        const uint4* bp = Bp + (size_t)tap * 256;

        uint32_t bf[4][8];
        #pragma unroll
        for (int sp = 0; sp < 8; sp++) {
            uint4 qv = bp[(size_t)sp * 32];
            const int s = sp >> 1, p = sp & 1;
            bf[s][p*4+0] = qv.x; bf[s][p*4+1] = qv.y;
            bf[s][p*4+2] = qv.z; bf[s][p*4+3] = qv.w;
        }

        uint32_t Ah0[2][4], Ah1[2][4], Al0[2][4], Al1[2][4];
        ldsm4(Ah0[0], aA0 + 0);  ldsm4(Ah1[0], aA0 + 32);
        ldsm4(Al0[0], aA0 + 64); ldsm4(Al1[0], aA0 + 96);
        ldsm4(Ah0[1], aA1 + 0);  ldsm4(Ah1[1], aA1 + 32);
        ldsm4(Al0[1], aA1 + 64); ldsm4(Al1[1], aA1 + 96);

        #pragma unroll
        for (int mt = 0; mt < 2; mt++)
            #pragma unroll
            for (int n = 0; n < 4; n++) {
                const int i0 = (n>>1)*4 + (n&1)*2;
                mma16816(acc[mt][n], Ah0[mt][0],Ah0[mt][1],Ah0[mt][2],Ah0[mt][3], bf[0][i0], bf[0][i0+1]);
                mma16816(acc[mt][n], Al0[mt][0],Al0[mt][1],Al0[mt][2],Al0[mt][3], bf[0][i0], bf[0][i0+1]);
                mma16816(acc[mt][n], Ah1[mt][0],Ah1[mt][1],Ah1[mt][2],Ah1[mt][3], bf[1][i0], bf[1][i0+1]);
                mma16816(acc[mt][n], Al1[mt][0],Al1[mt][1],Al1[mt][2],Al1[mt][3], bf[1][i0], bf[1][i0+1]);
                mma16816(acc[mt][n], Ah0[mt][0],Ah0[mt][1],Ah0[mt][2],Ah0[mt][3], bf[2][i0], bf[2][i0+1]);
                mma16816(acc[mt][n], Ah1[mt][0],Ah1[mt][1],Ah1[mt][2],Ah1[mt][3], bf[3][i0], bf[3][i0+1]);
            }
    }
}

// ---------------- state kernel (N-split; double-buffered A pipeline) ----------------
__global__ void __launch_bounds__(THREADS, 2)
state_kernel(const float* __restrict__ he, const float* __restrict__ hi,
             float* __restrict__ out)
{
    extern __shared__ char sm[];
    const uint32_t smb = smem_u32(sm);
    const int tid  = threadIdx.x;
    const int w    = tid >> 5;
    const int lane = tid & 31;
    const int gid  = lane >> 2;
    const int tig  = lane & 3;
    const int b    = blockIdx.z >> 1;
    const int half = blockIdx.z & 1;
    const int ty0  = blockIdx.y * 8;
    const int tx0  = blockIdx.x * 32;

    float acc[2][4][4];
    #pragma unroll
    for (int mt = 0; mt < 2; mt++)
        #pragma unroll
        for (int n = 0; n < 4; n++)
            #pragma unroll
            for (int q = 0; q < 4; q++) acc[mt][n][q] = 0.f;

    const int hbase = (w + 1) * 34 + 1;
    const uint32_t laneA0b = smb + (uint32_t)(hbase + (lane & 15)) * RS
                           + (uint32_t)((lane >> 4) << 4);

    // prologue: stage t=0 into buffer 0
    stage_A(sm, smb, 0, 0, b, ty0, tx0, tid);
    CP_COMMIT();

    #pragma unroll 1
    for (int t = 0; t < 3; t++) {
        if (t < 2) {                          // overlap: stage t+1 into other buffer
            stage_A(sm, smb, (uint32_t)((t + 1) & 1) * A_SZ, t + 1, b, ty0, tx0, tid);
            CP_COMMIT();
            CP_WAIT1();                       // oldest group (buffer t) landed
        } else {
            CP_WAIT0();
        }
        __syncthreads();

        const uint32_t laneA0 = laneA0b + (uint32_t)(t & 1) * A_SZ;
        const uint4* Bp = g_BfragSt + ((size_t)(t*2 + half) * 9) * 256 + lane;
        conv_tap_loop(acc, laneA0, laneA0 + 16u*RS, Bp);
        __syncthreads();                      // buffer t free for reuse at t+2
    }

    // epilogue + h_e_new bf16 row emission
    uint32_t* rowbase = (uint32_t*)(g_Arows + (size_t)3 * (Bn*HW) * 8);
    #pragma unroll
    for (int mt = 0; mt < 2; mt++) {
        #pragma unroll
        for (int hf = 0; hf < 2; hf++) {
            int px_local = mt*16 + gid + hf*8;
            int py = ty0 + w;
            int px = tx0 + px_local;
            size_t pidx = (size_t)b * CHW + (size_t)py * Ww + px;
            uint32_t* rp = rowbase + ((size_t)b * HW + (size_t)py * Ww + px) * 32;
            #pragma unroll
            for (int n = 0; n < 4; n++) {
                int cl = n*8 + 2*tig;
                int co = half*32 + cl;
                float a0 = acc[mt][n][hf*2]     + g_bcomb[co];
                float a1 = acc[mt][n][hf*2 + 1] + g_bcomb[co+1];
                float i0 = g_invtau[co], i1 = g_invtau[co+1];
                float c0 = fast_tanh(a0), c1 = fast_tanh(a1);
                if (half == 0) {
                    float h0 = (i0 < 1.f) ? he[pidx + (size_t)cl * HW]     : 0.f;
                    float h1 = (i1 < 1.f) ? he[pidx + (size_t)(cl+1) * HW] : 0.f;
                    float v0 = (1.f - i0)*h0 + i0*c0;
                    float v1 = (1.f - i1)*h1 + i1*c1;
                    out[(size_t)NTOT + pidx + (size_t)cl * HW]     = v0;
                    out[(size_t)NTOT + pidx + (size_t)(cl+1) * HW] = v1;
                    unsigned short h0b, l0b, h1b, l1b;
                    bf16split(v0, h0b, l0b);
                    bf16split(v1, h1b, l1b);
                    int widx = cl >> 1;
                    rp[widx]      = (uint32_t)h0b | ((uint32_t)h1b << 16);
                    rp[16 + widx] = (uint32_t)l0b | ((uint32_t)l1b << 16);
                } else {
                    float h0 = (i0 < 1.f) ? hi[pidx + (size_t)cl * HW]     : 0.f;
                    float h1 = (i1 < 1.f) ? hi[pidx + (size_t)(cl+1) * HW] : 0.f;
                    out[(size_t)2*NTOT + pidx + (size_t)cl * HW]     = (1.f - i0)*h0 + i0*c0;
                    out[(size_t)2*NTOT + pidx + (size_t)(cl+1) * HW] = (1.f - i1)*h1 + i1*c1;
                }
            }
        }
    }
}

// ---------------- out kernel ----------------
__global__ void __launch_bounds__(THREADS, 2)
out_kernel(float* __restrict__ out)
{
    extern __shared__ char sm[];
    const uint32_t smb = smem_u32(sm);
    const int tid  = threadIdx.x;
    const int w    = tid >> 5;
    const int lane = tid & 31;
    const int gid  = lane >> 2;
    const int tig  = lane & 3;
    const int b    = blockIdx.z;
    const int ty0  = blockIdx.y * 8;
    const int tx0  = blockIdx.x * 32;

    float acc[2][4][4];
    #pragma unroll
    for (int mt = 0; mt < 2; mt++)
        #pragma unroll
        for (int n = 0; n < 4; n++)
            #pragma unroll
            for (int q = 0; q < 4; q++) acc[mt][n][q] = 0.f;

    const int hbase = (w + 1) * 34 + 1;
    const uint32_t laneA0 = smb + (uint32_t)(hbase + (lane & 15)) * RS
                          + (uint32_t)((lane >> 4) << 4);

    stage_A(sm, smb, 0, 3, b, ty0, tx0, tid);
    CP_COMMIT();
    CP_WAIT0();
    __syncthreads();

    const uint4* Bp = g_BfragOut + lane;
    conv_tap_loop(acc, laneA0, laneA0 + 16u*RS, Bp);

    #pragma unroll
    for (int mt = 0; mt < 2; mt++) {
        #pragma unroll
        for (int hf = 0; hf < 2; hf++) {
            int px_local = mt*16 + gid + hf*8;
            int py = ty0 + w;
            int px = tx0 + px_local;
            size_t pidx = (size_t)b * CHW + (size_t)py * Ww + px;
            #pragma unroll
            for (int n = 0; n < 4; n++) {
                #pragma unroll
                for (int q = 0; q < 2; q++) {
                    int co  = n*8 + 2*tig + q;
                    float v = acc[mt][n][hf*2 + q] + g_bout[co];
                    out[pidx + (size_t)co * HW] = fast_tanh(v);
                }
            }
        }
    }
}

extern "C" void kernel_launch(void* const* d_in, const int* in_sizes, int n_in,
                              void* d_out, int out_size)
{
    (void)in_sizes; (void)n_in; (void)out_size;
    const float* x  = (const float*)d_in[0];
    const float* he = (const float*)d_in[1];
    const float* hi = (const float*)d_in[2];
    float* out = (float*)d_out;

    cudaFuncSetAttribute(state_kernel, cudaFuncAttributeMaxDynamicSharedMemorySize, SMEM_T);
    cudaFuncSetAttribute(out_kernel,   cudaFuncAttributeMaxDynamicSharedMemorySize, A_SZ);

    prep_kernel<<<63, 256>>>(
        (const float*)d_in[3],  (const float*)d_in[4],
        (const float*)d_in[5],  (const float*)d_in[6],
        (const float*)d_in[7],  (const float*)d_in[8],
        (const float*)d_in[9],  (const float*)d_in[10],
        (const float*)d_in[11], (const float*)d_in[12],
        (const float*)d_in[13], (const float*)d_in[14],
        (const float*)d_in[15], (const float*)d_in[16],
        (const float*)d_in[17], (const float*)d_in[18]);

    convert_kernel<<<(3*Bn*HW)/256, 256>>>(x, he, hi);

    dim3 gs(4, 16, Bn*2);   // x-tiles, y-tiles, batch x co-half
    state_kernel<<<gs, THREADS, SMEM_T>>>(he, hi, out);
    dim3 go(4, 16, Bn);
    out_kernel<<<go, THREADS, A_SZ>>>(out);
}

// round 13
// speedup vs baseline: 1.4993x; 1.4849x over previous
#include <cuda_runtime.h>
#include <math.h>
#include <stdint.h>

#define Bn 16
#define Cc 32
#define Hh 128
#define Ww 128
#define HW (Hh*Ww)
#define CHW (Cc*HW)
#define NTOT (Bn*CHW)

// block tile: 8 out rows x 32 out cols = 256 px; halo 10x34 = 340 A rows
#define THREADS 256
#define NROWS 340

#define RS     80                     // SMEM row stride: 64B fp16 data + 16 pad (conflict-free ldsm)
#define A_SZ   (NROWS*RS)             // 27200 bytes per buffer
#define SMEM_T (2*A_SZ)               // 54400: double-buffered A

#define WSCL   2048.0f                // weight pre-scale (keeps Wlo fp16-normal)
#define WINV   (1.0f/2048.0f)

// global A-row images: [t(4)][b*HW + pix] rows of 64B (32ci fp16), dense
__device__ uint4 g_Arows[(size_t)4*Bn*HW*4];

// B fragment tables, register-image order:
// state: [t(3)][half(2)][tap(9)][plane(2)][s(2)][p(2)][lane(32)] -> 13824 uint4
// out:   [tap(9)][plane(2)][s(2)][p(2)][lane(32)]                -> 2304 uint4
#define STFRAG (3*2*9*2*2*2*32)
#define OUTFRAG (9*2*2*2*32)
__device__ __align__(16) uint4 g_BfragSt[STFRAG];
__device__ __align__(16) uint4 g_BfragOut[OUTFRAG];
__device__ float g_bcomb[64];
__device__ float g_bout[32];
__device__ float g_invtau[64];

// ---------------- helpers ----------------
__device__ __forceinline__ uint32_t smem_u32(const void* p) {
    uint32_t a;
    asm("{ .reg .u64 t; cvta.to.shared.u64 t, %1; cvt.u32.u64 %0, t; }" : "=r"(a) : "l"(p));
    return a;
}
__device__ __forceinline__ unsigned short f2h(float v) {
    unsigned short h;
    asm("cvt.rn.f16.f32 %0, %1;" : "=h"(h) : "f"(v));
    return h;
}
__device__ __forceinline__ float h2f(unsigned short h) {
    float f;
    asm("cvt.f32.f16 %0, %1;" : "=f"(f) : "h"(h));
    return f;
}
__device__ __forceinline__ float fast_tanh(float x) {
    float e, r;
    asm("ex2.approx.f32 %0, %1;" : "=f"(e) : "f"(x * 2.8853900817779268f));
    asm("rcp.approx.f32 %0, %1;" : "=f"(r) : "f"(e + 1.f));
    return fmaf(-2.f, r, 1.f);
}
__device__ __forceinline__ void mma16816(float* c,
    uint32_t a0, uint32_t a1, uint32_t a2, uint32_t a3, uint32_t b0, uint32_t b1)
{
    asm volatile(
        "mma.sync.aligned.m16n8k16.row.col.f32.f16.f16.f32 "
        "{%0,%1,%2,%3}, {%4,%5,%6,%7}, {%8,%9}, {%0,%1,%2,%3};"
        : "+f"(c[0]), "+f"(c[1]), "+f"(c[2]), "+f"(c[3])
        : "r"(a0), "r"(a1), "r"(a2), "r"(a3), "r"(b0), "r"(b1));
}
__device__ __forceinline__ void ldsm4(uint32_t* r, uint32_t addr) {
    asm volatile("ldmatrix.sync.aligned.m8n8.x4.shared.b16 {%0,%1,%2,%3}, [%4];"
        : "=r"(r[0]), "=r"(r[1]), "=r"(r[2]), "=r"(r[3]) : "r"(addr));
}
__device__ __forceinline__ void cp16(uint32_t smdst, const void* gsrc) {
    asm volatile("cp.async.cg.shared.global [%0], [%1], 16;" :: "r"(smdst), "l"(gsrc));
}
#define CP_COMMIT() asm volatile("cp.async.commit_group;" ::: "memory")
#define CP_WAIT0()  asm volatile("cp.async.wait_group 0;" ::: "memory")
#define CP_WAIT1()  asm volatile("cp.async.wait_group 1;" ::: "memory")

// ---------------- prep: Dale fold, x2048 scale, fp16 hi/lo split, FRAGMENT order ----------------
__global__ void prep_kernel(
    const float* __restrict__ W_in_e, const float* __restrict__ b_in_e,
    const float* __restrict__ W_in_i, const float* __restrict__ b_in_i,
    const float* __restrict__ W_e_e,  const float* __restrict__ b_e_e,
    const float* __restrict__ W_e_i,  const float* __restrict__ b_e_i,
    const float* __restrict__ W_e_out,const float* __restrict__ b_e_out,
    const float* __restrict__ W_i_e,  const float* __restrict__ b_i_e,
    const float* __restrict__ W_i_i,  const float* __restrict__ b_i_i,
    const float* __restrict__ tau_e,  const float* __restrict__ tau_i)
{
    int fid = blockIdx.x * 256 + threadIdx.x;
    if (fid < STFRAG) {
        int lane = fid & 31;
        int q    = fid >> 5;
        int p     = q & 1;  q >>= 1;
        int s     = q & 1;  q >>= 1;
        int plane = q & 1;  q >>= 1;
        int tap   = q % 9;  q /= 9;
        int half  = q & 1;
        int t     = q >> 1;
        uint32_t comp[4];
        #pragma unroll
        for (int j = 0; j < 4; j++) {
            int co_l = p*16 + ((j>>1)<<3) + (lane>>2);
            int ci   = s*16 + ((j&1)<<3) + ((lane&3)<<1);
            unsigned short v[2];
            #pragma unroll
            for (int e = 0; e < 2; e++) {
                int src = co_l * 288 + (ci + e) * 9 + tap;   // OIHW
                float w;
                if (t == 0)      w = (half == 0) ? W_in_e[src] : W_in_i[src];
                else if (t == 1) w = fmaxf((half == 0) ? W_e_e[src] : W_e_i[src], 0.f);
                else             w = -fmaxf((half == 0) ? W_i_e[src] : W_i_i[src], 0.f);
                w *= WSCL;
                unsigned short hh = f2h(w);
                v[e] = plane ? f2h(w - h2f(hh)) : hh;
            }
            comp[j] = (uint32_t)v[0] | ((uint32_t)v[1] << 16);
        }
        g_BfragSt[fid] = make_uint4(comp[0], comp[1], comp[2], comp[3]);
    } else if (fid < STFRAG + OUTFRAG) {
        int f2   = fid - STFRAG;
        int lane = f2 & 31;
        int q    = f2 >> 5;
        int p     = q & 1;  q >>= 1;
        int s     = q & 1;  q >>= 1;
        int plane = q & 1;  q >>= 1;
        int tap   = q;
        uint32_t comp[4];
        #pragma unroll
        for (int j = 0; j < 4; j++) {
            int co_l = p*16 + ((j>>1)<<3) + (lane>>2);
            int ci   = s*16 + ((j&1)<<3) + ((lane&3)<<1);
            unsigned short v[2];
            #pragma unroll
            for (int e = 0; e < 2; e++) {
                float w = fmaxf(W_e_out[co_l*288 + (ci + e)*9 + tap], 0.f) * WSCL;
                unsigned short hh = f2h(w);
                v[e] = plane ? f2h(w - h2f(hh)) : hh;
            }
            comp[j] = (uint32_t)v[0] | ((uint32_t)v[1] << 16);
        }
        g_BfragOut[f2] = make_uint4(comp[0], comp[1], comp[2], comp[3]);
    }
    if (blockIdx.x == 0 && threadIdx.x < 64) {
        int co = threadIdx.x;
        if (co < 32) {
            g_bcomb[co]  = b_in_e[co] + fmaxf(b_e_e[co], 0.f) - fmaxf(b_i_e[co], 0.f);
            g_invtau[co] = 1.f / fmaxf(tau_e[co], 1.f);
            g_bout[co]   = fmaxf(b_e_out[co], 0.f);
        } else {
            int c = co - 32;
            g_bcomb[co]  = b_in_i[c] + fmaxf(b_e_i[c], 0.f) - fmaxf(b_i_i[c], 0.f);
            g_invtau[co] = 1.f / fmaxf(tau_i[c], 1.f);
        }
    }
}

// ---------------- convert: NCHW fp32 -> per-pixel 64B fp16 rows ----------------
__global__ void __launch_bounds__(256)
convert_kernel(const float* __restrict__ x, const float* __restrict__ he,
               const float* __restrict__ hi)
{
    int gidx = blockIdx.x * 256 + threadIdx.x;
    int t = gidx / (Bn*HW);
    int p = gidx - t * (Bn*HW);
    int b = p / HW;
    int pix = p - b * HW;
    const float* src = (t == 0 ? x : (t == 1 ? he : hi)) + (size_t)b * CHW + pix;
    uint4* dst = g_Arows + ((size_t)t * (Bn*HW) + p) * 4;

    uint32_t hw[16];
    #pragma unroll
    for (int k = 0; k < 16; k++) {
        unsigned short h0 = f2h(src[(size_t)(2*k)   * HW]);
        unsigned short h1 = f2h(src[(size_t)(2*k+1) * HW]);
        hw[k] = (uint32_t)h0 | ((uint32_t)h1 << 16);
    }
    #pragma unroll
    for (int j = 0; j < 4; j++)
        dst[j] = make_uint4(hw[4*j], hw[4*j+1], hw[4*j+2], hw[4*j+3]);
}

// ---------------- A tile staging: 64B rows, division-free ----------------
__device__ __forceinline__ void stage_A(char* sm, uint32_t smb, uint32_t a_off,
                                        int t, int b, int ty0, int tx0, int tid)
{
    const char* gb = (const char*)g_Arows + ((size_t)t * (Bn*HW) + (size_t)b * HW) * 64;
    const int c   = tid & 3;          // 16B chunk within 64B row
    const int col = tid >> 2;         // 0..63; only col<34 active
    if (col >= 34) return;

    const int gx   = tx0 + col - 1;
    const bool okx = ((unsigned)gx < 128u);
    uint32_t dst = smb + a_off + (uint32_t)col * RS + (uint32_t)c * 16;
    const char* src = gb + ((size_t)(ty0 - 1) * Ww + gx) * 64 + c * 16;

    #pragma unroll
    for (int ry = 0; ry < 10; ry++) {
        const int gy = ty0 + ry - 1;
        if (((unsigned)gy < 128u) && okx) cp16(dst, src);
        else                              *(uint4*)(sm + (dst - smb)) = make_uint4(0,0,0,0);
        dst += 34u * RS;
        src += (size_t)Ww * 64;
    }
}

// ---------------- mainloop: 2-pass fp16 (A single, W hi+lo), 9 taps ----------------
__device__ __forceinline__ void conv_tap_loop(
    float acc[2][4][4], const uint32_t laneA0, const uint32_t laneA1,
    const uint4* __restrict__ Bp)
{
    #pragma unroll 1
    for (int tap = 0; tap < 9; tap++) {
        const int soff = ((tap/3) - 1) * (34*RS) + ((tap % 3) - 1) * RS;
        const uint32_t aA0 = laneA0 + soff;
        const uint32_t aA1 = laneA1 + soff;
        const uint4* bp = Bp + (size_t)tap * 256;

        // B fragments: 8 coalesced LDG.128 (L1-resident). g = plane*4 + s*2 + p
        uint32_t bh[2][8], bl[2][8];
        #pragma unroll
        for (int g = 0; g < 8; g++) {
            uint4 qv = bp[(size_t)g * 32];
            const int s = (g >> 1) & 1, p = g & 1;
            uint32_t* dstp = (g >> 2) ? bl[s] : bh[s];
            dstp[p*4+0] = qv.x; dstp[p*4+1] = qv.y;
            dstp[p*4+2] = qv.z; dstp[p*4+3] = qv.w;
        }

        // A fragments: 4 ldmatrix.x4 (mt x kset)
        uint32_t Aa[2][2][4];
        ldsm4(Aa[0][0], aA0 + 0);  ldsm4(Aa[0][1], aA0 + 32);
        ldsm4(Aa[1][0], aA1 + 0);  ldsm4(Aa[1][1], aA1 + 32);

        #pragma unroll
        for (int mt = 0; mt < 2; mt++)
            #pragma unroll
            for (int n = 0; n < 4; n++) {
                const int i0 = (n>>1)*4 + (n&1)*2;
                mma16816(acc[mt][n], Aa[mt][0][0],Aa[mt][0][1],Aa[mt][0][2],Aa[mt][0][3], bh[0][i0], bh[0][i0+1]);
                mma16816(acc[mt][n], Aa[mt][0][0],Aa[mt][0][1],Aa[mt][0][2],Aa[mt][0][3], bl[0][i0], bl[0][i0+1]);
                mma16816(acc[mt][n], Aa[mt][1][0],Aa[mt][1][1],Aa[mt][1][2],Aa[mt][1][3], bh[1][i0], bh[1][i0+1]);
                mma16816(acc[mt][n], Aa[mt][1][0],Aa[mt][1][1],Aa[mt][1][2],Aa[mt][1][3], bl[1][i0], bl[1][i0+1]);
            }
    }
}

// ---------------- state kernel (N-split; double-buffered A pipeline) ----------------
__global__ void __launch_bounds__(THREADS, 2)
state_kernel(const float* __restrict__ he, const float* __restrict__ hi,
             float* __restrict__ out)
{
    extern __shared__ char sm[];
    const uint32_t smb = smem_u32(sm);
    const int tid  = threadIdx.x;
    const int w    = tid >> 5;
    const int lane = tid & 31;
    const int gid  = lane >> 2;
    const int tig  = lane & 3;
    const int b    = blockIdx.z >> 1;
    const int half = blockIdx.z & 1;
    const int ty0  = blockIdx.y * 8;
    const int tx0  = blockIdx.x * 32;

    float acc[2][4][4];
    #pragma unroll
    for (int mt = 0; mt < 2; mt++)
        #pragma unroll
        for (int n = 0; n < 4; n++)
            #pragma unroll
            for (int q = 0; q < 4; q++) acc[mt][n][q] = 0.f;

    const int hbase = (w + 1) * 34 + 1;
    const uint32_t laneA0b = smb + (uint32_t)(hbase + (lane & 15)) * RS
                           + (uint32_t)((lane >> 4) << 4);

    stage_A(sm, smb, 0, 0, b, ty0, tx0, tid);
    CP_COMMIT();

    #pragma unroll 1
    for (int t = 0; t < 3; t++) {
        if (t < 2) {
            stage_A(sm, smb, (uint32_t)((t + 1) & 1) * A_SZ, t + 1, b, ty0, tx0, tid);
            CP_COMMIT();
            CP_WAIT1();
        } else {
            CP_WAIT0();
        }
        __syncthreads();

        const uint32_t laneA0 = laneA0b + (uint32_t)(t & 1) * A_SZ;
        const uint4* Bp = g_BfragSt + ((size_t)(t*2 + half) * 9) * 256 + lane;
        conv_tap_loop(acc, laneA0, laneA0 + 16u*RS, Bp);
        __syncthreads();
    }

    // epilogue: unscale, bias, tanh, leaky integrate; emit h_e_new fp16 rows
    uint32_t* rowbase = (uint32_t*)(g_Arows + (size_t)3 * (Bn*HW) * 4);
    #pragma unroll
    for (int mt = 0; mt < 2; mt++) {
        #pragma unroll
        for (int hf = 0; hf < 2; hf++) {
            int px_local = mt*16 + gid + hf*8;
            int py = ty0 + w;
            int px = tx0 + px_local;
            size_t pidx = (size_t)b * CHW + (size_t)py * Ww + px;
            uint32_t* rp = rowbase + ((size_t)b * HW + (size_t)py * Ww + px) * 16;
            #pragma unroll
            for (int n = 0; n < 4; n++) {
                int cl = n*8 + 2*tig;
                int co = half*32 + cl;
                float a0 = acc[mt][n][hf*2]     * WINV + g_bcomb[co];
                float a1 = acc[mt][n][hf*2 + 1] * WINV + g_bcomb[co+1];
                float i0 = g_invtau[co], i1 = g_invtau[co+1];
                float c0 = fast_tanh(a0), c1 = fast_tanh(a1);
                if (half == 0) {
                    float h0 = (i0 < 1.f) ? he[pidx + (size_t)cl * HW]     : 0.f;
                    float h1 = (i1 < 1.f) ? he[pidx + (size_t)(cl+1) * HW] : 0.f;
                    float v0 = (1.f - i0)*h0 + i0*c0;
                    float v1 = (1.f - i1)*h1 + i1*c1;
                    out[(size_t)NTOT + pidx + (size_t)cl * HW]     = v0;
                    out[(size_t)NTOT + pidx + (size_t)(cl+1) * HW] = v1;
                    rp[cl >> 1] = (uint32_t)f2h(v0) | ((uint32_t)f2h(v1) << 16);
                } else {
                    float h0 = (i0 < 1.f) ? hi[pidx + (size_t)cl * HW]     : 0.f;
                    float h1 = (i1 < 1.f) ? hi[pidx + (size_t)(cl+1) * HW] : 0.f;
                    out[(size_t)2*NTOT + pidx + (size_t)cl * HW]     = (1.f - i0)*h0 + i0*c0;
                    out[(size_t)2*NTOT + pidx + (size_t)(cl+1) * HW] = (1.f - i1)*h1 + i1*c1;
                }
            }
        }
    }
}

// ---------------- out kernel ----------------
__global__ void __launch_bounds__(THREADS, 2)
out_kernel(float* __restrict__ out)
{
    extern __shared__ char sm[];
    const uint32_t smb = smem_u32(sm);
    const int tid  = threadIdx.x;
    const int w    = tid >> 5;
    const int lane = tid & 31;
    const int gid  = lane >> 2;
    const int tig  = lane & 3;
    const int b    = blockIdx.z;
    const int ty0  = blockIdx.y * 8;
    const int tx0  = blockIdx.x * 32;

    float acc[2][4][4];
    #pragma unroll
    for (int mt = 0; mt < 2; mt++)
        #pragma unroll
        for (int n = 0; n < 4; n++)
            #pragma unroll
            for (int q = 0; q < 4; q++) acc[mt][n][q] = 0.f;

    const int hbase = (w + 1) * 34 + 1;
    const uint32_t laneA0 = smb + (uint32_t)(hbase + (lane & 15)) * RS
                          + (uint32_t)((lane >> 4) << 4);

    stage_A(sm, smb, 0, 3, b, ty0, tx0, tid);
    CP_COMMIT();
    CP_WAIT0();
    __syncthreads();

    const uint4* Bp = g_BfragOut + lane;
    conv_tap_loop(acc, laneA0, laneA0 + 16u*RS, Bp);

    #pragma unroll
    for (int mt = 0; mt < 2; mt++) {
        #pragma unroll
        for (int hf = 0; hf < 2; hf++) {
            int px_local = mt*16 + gid + hf*8;
            int py = ty0 + w;
            int px = tx0 + px_local;
            size_t pidx = (size_t)b * CHW + (size_t)py * Ww + px;
            #pragma unroll
            for (int n = 0; n < 4; n++) {
                #pragma unroll
                for (int q = 0; q < 2; q++) {
                    int co  = n*8 + 2*tig + q;
                    float v = acc[mt][n][hf*2 + q] * WINV + g_bout[co];
                    out[pidx + (size_t)co * HW] = fast_tanh(v);
                }
            }
        }
    }
}

extern "C" void kernel_launch(void* const* d_in, const int* in_sizes, int n_in,
                              void* d_out, int out_size)
{
    (void)in_sizes; (void)n_in; (void)out_size;
    const float* x  = (const float*)d_in[0];
    const float* he = (const float*)d_in[1];
    const float* hi = (const float*)d_in[2];
    float* out = (float*)d_out;

    cudaFuncSetAttribute(state_kernel, cudaFuncAttributeMaxDynamicSharedMemorySize, SMEM_T);
    cudaFuncSetAttribute(out_kernel,   cudaFuncAttributeMaxDynamicSharedMemorySize, A_SZ);

    prep_kernel<<<63, 256>>>(
        (const float*)d_in[3],  (const float*)d_in[4],
        (const float*)d_in[5],  (const float*)d_in[6],
        (const float*)d_in[7],  (const float*)d_in[8],
        (const float*)d_in[9],  (const float*)d_in[10],
        (const float*)d_in[11], (const float*)d_in[12],
        (const float*)d_in[13], (const float*)d_in[14],
        (const float*)d_in[15], (const float*)d_in[16],
        (const float*)d_in[17], (const float*)d_in[18]);

    convert_kernel<<<(3*Bn*HW)/256, 256>>>(x, he, hi);

    dim3 gs(4, 16, Bn*2);   // x-tiles, y-tiles, batch x co-half
    state_kernel<<<gs, THREADS, SMEM_T>>>(he, hi, out);
    dim3 go(4, 16, Bn);
    out_kernel<<<go, THREADS, A_SZ>>>(out);
}

// round 14
// speedup vs baseline: 1.5856x; 1.0576x over previous
#include <cuda_runtime.h>
#include <math.h>
#include <stdint.h>

#define Bn 16
#define Cc 32
#define Hh 128
#define Ww 128
#define HW (Hh*Ww)
#define CHW (Cc*HW)
#define NTOT (Bn*CHW)

// block tile: 8 out rows x 32 out cols = 256 px; halo 10x34 = 340 A rows
#define THREADS 256
#define NROWS 340

#define RS     80                     // SMEM row stride: 64B fp16 data + 16 pad
#define A_SZ   (NROWS*RS)             // 27200 bytes per buffer
#define SMEM_T (2*A_SZ)               // 54400: double-buffered A

#define WSCL   2048.0f
#define WINV   (1.0f/2048.0f)

// global A-row images: [t(4)][b*HW + pix] rows of 64B (32ci fp16), dense
__device__ uint4 g_Arows[(size_t)4*Bn*HW*4];

// B fragment tables, register-image order:
// state: [t(3)][half(2)][tap(9)][plane(2)][s(2)][p(2)][lane(32)] -> 13824 uint4
// out:   [tap(9)][plane(2)][s(2)][p(2)][lane(32)]                -> 2304 uint4
#define STFRAG (3*2*9*2*2*2*32)
#define OUTFRAG (9*2*2*2*32)
__device__ __align__(16) uint4 g_BfragSt[STFRAG];
__device__ __align__(16) uint4 g_BfragOut[OUTFRAG];
__device__ float g_bcomb[64];
__device__ float g_bout[32];
__device__ float g_invtau[64];

// ---------------- helpers ----------------
__device__ __forceinline__ uint32_t smem_u32(const void* p) {
    uint32_t a;
    asm("{ .reg .u64 t; cvta.to.shared.u64 t, %1; cvt.u32.u64 %0, t; }" : "=r"(a) : "l"(p));
    return a;
}
__device__ __forceinline__ unsigned short f2h(float v) {
    unsigned short h;
    asm("cvt.rn.f16.f32 %0, %1;" : "=h"(h) : "f"(v));
    return h;
}
__device__ __forceinline__ float h2f(unsigned short h) {
    float f;
    asm("cvt.f32.f16 %0, %1;" : "=f"(f) : "h"(h));
    return f;
}
__device__ __forceinline__ float fast_tanh(float x) {
    float e, r;
    asm("ex2.approx.f32 %0, %1;" : "=f"(e) : "f"(x * 2.8853900817779268f));
    asm("rcp.approx.f32 %0, %1;" : "=f"(r) : "f"(e + 1.f));
    return fmaf(-2.f, r, 1.f);
}
__device__ __forceinline__ void mma16816(float* c,
    uint32_t a0, uint32_t a1, uint32_t a2, uint32_t a3, uint32_t b0, uint32_t b1)
{
    asm volatile(
        "mma.sync.aligned.m16n8k16.row.col.f32.f16.f16.f32 "
        "{%0,%1,%2,%3}, {%4,%5,%6,%7}, {%8,%9}, {%0,%1,%2,%3};"
        : "+f"(c[0]), "+f"(c[1]), "+f"(c[2]), "+f"(c[3])
        : "r"(a0), "r"(a1), "r"(a2), "r"(a3), "r"(b0), "r"(b1));
}
__device__ __forceinline__ void ldsm4(uint32_t* r, uint32_t addr) {
    asm volatile("ldmatrix.sync.aligned.m8n8.x4.shared.b16 {%0,%1,%2,%3}, [%4];"
        : "=r"(r[0]), "=r"(r[1]), "=r"(r[2]), "=r"(r[3]) : "r"(addr));
}
__device__ __forceinline__ void cp16(uint32_t smdst, const void* gsrc) {
    asm volatile("cp.async.cg.shared.global [%0], [%1], 16;" :: "r"(smdst), "l"(gsrc));
}
#define CP_COMMIT() asm volatile("cp.async.commit_group;" ::: "memory")
#define CP_WAIT0()  asm volatile("cp.async.wait_group 0;" ::: "memory")
#define CP_WAIT1()  asm volatile("cp.async.wait_group 1;" ::: "memory")

// ---------------- prep: Dale fold, x2048 scale, fp16 hi/lo split, FRAGMENT order ----------------
__global__ void prep_kernel(
    const float* __restrict__ W_in_e, const float* __restrict__ b_in_e,
    const float* __restrict__ W_in_i, const float* __restrict__ b_in_i,
    const float* __restrict__ W_e_e,  const float* __restrict__ b_e_e,
    const float* __restrict__ W_e_i,  const float* __restrict__ b_e_i,
    const float* __restrict__ W_e_out,const float* __restrict__ b_e_out,
    const float* __restrict__ W_i_e,  const float* __restrict__ b_i_e,
    const float* __restrict__ W_i_i,  const float* __restrict__ b_i_i,
    const float* __restrict__ tau_e,  const float* __restrict__ tau_i)
{
    int fid = blockIdx.x * 256 + threadIdx.x;
    if (fid < STFRAG) {
        int lane = fid & 31;
        int q    = fid >> 5;
        int p     = q & 1;  q >>= 1;
        int s     = q & 1;  q >>= 1;
        int plane = q & 1;  q >>= 1;
        int tap   = q % 9;  q /= 9;
        int half  = q & 1;
        int t     = q >> 1;
        uint32_t comp[4];
        #pragma unroll
        for (int j = 0; j < 4; j++) {
            int co_l = p*16 + ((j>>1)<<3) + (lane>>2);
            int ci   = s*16 + ((j&1)<<3) + ((lane&3)<<1);
            unsigned short v[2];
            #pragma unroll
            for (int e = 0; e < 2; e++) {
                int src = co_l * 288 + (ci + e) * 9 + tap;   // OIHW
                float w;
                if (t == 0)      w = (half == 0) ? W_in_e[src] : W_in_i[src];
                else if (t == 1) w = fmaxf((half == 0) ? W_e_e[src] : W_e_i[src], 0.f);
                else             w = -fmaxf((half == 0) ? W_i_e[src] : W_i_i[src], 0.f);
                w *= WSCL;
                unsigned short hh = f2h(w);
                v[e] = plane ? f2h(w - h2f(hh)) : hh;
            }
            comp[j] = (uint32_t)v[0] | ((uint32_t)v[1] << 16);
        }
        g_BfragSt[fid] = make_uint4(comp[0], comp[1], comp[2], comp[3]);
    } else if (fid < STFRAG + OUTFRAG) {
        int f2   = fid - STFRAG;
        int lane = f2 & 31;
        int q    = f2 >> 5;
        int p     = q & 1;  q >>= 1;
        int s     = q & 1;  q >>= 1;
        int plane = q & 1;  q >>= 1;
        int tap   = q;
        uint32_t comp[4];
        #pragma unroll
        for (int j = 0; j < 4; j++) {
            int co_l = p*16 + ((j>>1)<<3) + (lane>>2);
            int ci   = s*16 + ((j&1)<<3) + ((lane&3)<<1);
            unsigned short v[2];
            #pragma unroll
            for (int e = 0; e < 2; e++) {
                float w = fmaxf(W_e_out[co_l*288 + (ci + e)*9 + tap], 0.f) * WSCL;
                unsigned short hh = f2h(w);
                v[e] = plane ? f2h(w - h2f(hh)) : hh;
            }
            comp[j] = (uint32_t)v[0] | ((uint32_t)v[1] << 16);
        }
        g_BfragOut[f2] = make_uint4(comp[0], comp[1], comp[2], comp[3]);
    }
    if (blockIdx.x == 0 && threadIdx.x < 64) {
        int co = threadIdx.x;
        if (co < 32) {
            g_bcomb[co]  = b_in_e[co] + fmaxf(b_e_e[co], 0.f) - fmaxf(b_i_e[co], 0.f);
            g_invtau[co] = 1.f / fmaxf(tau_e[co], 1.f);
            g_bout[co]   = fmaxf(b_e_out[co], 0.f);
        } else {
            int c = co - 32;
            g_bcomb[co]  = b_in_i[c] + fmaxf(b_e_i[c], 0.f) - fmaxf(b_i_i[c], 0.f);
            g_invtau[co] = 1.f / fmaxf(tau_i[c], 1.f);
        }
    }
}

// ---------------- convert: NCHW fp32 -> per-pixel 64B fp16 rows ----------------
__global__ void __launch_bounds__(256)
convert_kernel(const float* __restrict__ x, const float* __restrict__ he,
               const float* __restrict__ hi)
{
    int gidx = blockIdx.x * 256 + threadIdx.x;
    int t = gidx / (Bn*HW);
    int p = gidx - t * (Bn*HW);
    int b = p / HW;
    int pix = p - b * HW;
    const float* src = (t == 0 ? x : (t == 1 ? he : hi)) + (size_t)b * CHW + pix;
    uint4* dst = g_Arows + ((size_t)t * (Bn*HW) + p) * 4;

    uint32_t hw[16];
    #pragma unroll
    for (int k = 0; k < 16; k++) {
        unsigned short h0 = f2h(src[(size_t)(2*k)   * HW]);
        unsigned short h1 = f2h(src[(size_t)(2*k+1) * HW]);
        hw[k] = (uint32_t)h0 | ((uint32_t)h1 << 16);
    }
    #pragma unroll
    for (int j = 0; j < 4; j++)
        dst[j] = make_uint4(hw[4*j], hw[4*j+1], hw[4*j+2], hw[4*j+3]);
}

// ---------------- A tile staging: 64B rows, division-free ----------------
__device__ __forceinline__ void stage_A(char* sm, uint32_t smb, uint32_t a_off,
                                        int t, int b, int ty0, int tx0, int tid)
{
    const char* gb = (const char*)g_Arows + ((size_t)t * (Bn*HW) + (size_t)b * HW) * 64;
    const int c   = tid & 3;
    const int col = tid >> 2;
    if (col >= 34) return;

    const int gx   = tx0 + col - 1;
    const bool okx = ((unsigned)gx < 128u);
    uint32_t dst = smb + a_off + (uint32_t)col * RS + (uint32_t)c * 16;
    const char* src = gb + ((size_t)(ty0 - 1) * Ww + gx) * 64 + c * 16;

    #pragma unroll
    for (int ry = 0; ry < 10; ry++) {
        const int gy = ty0 + ry - 1;
        if (((unsigned)gy < 128u) && okx) cp16(dst, src);
        else                              *(uint4*)(sm + (dst - smb)) = make_uint4(0,0,0,0);
        dst += 34u * RS;
        src += (size_t)Ww * 64;
    }
}

// load a tap's 8 B fragments (flat reg image: [g(plane*4+s*2+p)][4])
__device__ __forceinline__ void load_B(const uint4* __restrict__ bp, uint32_t* bf) {
    #pragma unroll
    for (int g = 0; g < 8; g++) {
        uint4 qv = bp[(size_t)g * 32];
        bf[g*4+0] = qv.x; bf[g*4+1] = qv.y; bf[g*4+2] = qv.z; bf[g*4+3] = qv.w;
    }
}

// ---------------- mainloop: 2-pass fp16, fully unrolled, B reg-pipelined across taps ----------------
__device__ __forceinline__ void conv_tap_loop(
    float acc[2][4][4], const uint32_t laneA0, const uint32_t laneA1,
    const uint4* __restrict__ Bp)
{
    uint32_t B[2][32];
    load_B(Bp, B[0]);

    #pragma unroll
    for (int tap = 0; tap < 9; tap++) {
        // prefetch next tap's B fragments (latency hidden behind this tap's MMAs)
        if (tap < 8) load_B(Bp + (size_t)(tap + 1) * 256, B[(tap + 1) & 1]);

        const int soff = ((tap/3) - 1) * (34*RS) + ((tap % 3) - 1) * RS;
        uint32_t Aa[2][2][4];
        ldsm4(Aa[0][0], laneA0 + soff + 0);  ldsm4(Aa[0][1], laneA0 + soff + 32);
        ldsm4(Aa[1][0], laneA1 + soff + 0);  ldsm4(Aa[1][1], laneA1 + soff + 32);

        const uint32_t* bc = B[tap & 1];
        #pragma unroll
        for (int mt = 0; mt < 2; mt++)
            #pragma unroll
            for (int n = 0; n < 4; n++) {
                const int p = n >> 1, q = (n & 1) * 2;
                const int ih0 = (0*2 + p)*4 + q;        // hi, s=0
                const int ih1 = (1*2 + p)*4 + q;        // hi, s=1
                const int il0 = 16 + (0*2 + p)*4 + q;   // lo, s=0
                const int il1 = 16 + (1*2 + p)*4 + q;   // lo, s=1
                mma16816(acc[mt][n], Aa[mt][0][0],Aa[mt][0][1],Aa[mt][0][2],Aa[mt][0][3], bc[ih0], bc[ih0+1]);
                mma16816(acc[mt][n], Aa[mt][0][0],Aa[mt][0][1],Aa[mt][0][2],Aa[mt][0][3], bc[il0], bc[il0+1]);
                mma16816(acc[mt][n], Aa[mt][1][0],Aa[mt][1][1],Aa[mt][1][2],Aa[mt][1][3], bc[ih1], bc[ih1+1]);
                mma16816(acc[mt][n], Aa[mt][1][0],Aa[mt][1][1],Aa[mt][1][2],Aa[mt][1][3], bc[il1], bc[il1+1]);
            }
    }
}

// ---------------- state kernel (N-split; double-buffered A pipeline) ----------------
__global__ void __launch_bounds__(THREADS, 2)
state_kernel(const float* __restrict__ he, const float* __restrict__ hi,
             float* __restrict__ out)
{
    extern __shared__ char sm[];
    const uint32_t smb = smem_u32(sm);
    const int tid  = threadIdx.x;
    const int w    = tid >> 5;
    const int lane = tid & 31;
    const int gid  = lane >> 2;
    const int tig  = lane & 3;
    const int b    = blockIdx.z >> 1;
    const int half = blockIdx.z & 1;
    const int ty0  = blockIdx.y * 8;
    const int tx0  = blockIdx.x * 32;

    float acc[2][4][4];
    #pragma unroll
    for (int mt = 0; mt < 2; mt++)
        #pragma unroll
        for (int n = 0; n < 4; n++)
            #pragma unroll
            for (int q = 0; q < 4; q++) acc[mt][n][q] = 0.f;

    const int hbase = (w + 1) * 34 + 1;
    const uint32_t laneA0b = smb + (uint32_t)(hbase + (lane & 15)) * RS
                           + (uint32_t)((lane >> 4) << 4);

    stage_A(sm, smb, 0, 0, b, ty0, tx0, tid);
    CP_COMMIT();

    #pragma unroll 1
    for (int t = 0; t < 3; t++) {
        if (t < 2) {
            stage_A(sm, smb, (uint32_t)((t + 1) & 1) * A_SZ, t + 1, b, ty0, tx0, tid);
            CP_COMMIT();
            CP_WAIT1();
        } else {
            CP_WAIT0();
        }
        __syncthreads();

        const uint32_t laneA0 = laneA0b + (uint32_t)(t & 1) * A_SZ;
        const uint4* Bp = g_BfragSt + ((size_t)(t*2 + half) * 9) * 256 + lane;
        conv_tap_loop(acc, laneA0, laneA0 + 16u*RS, Bp);
        __syncthreads();
    }

    // epilogue: unscale, bias, tanh, leaky integrate; emit h_e_new fp16 rows
    uint32_t* rowbase = (uint32_t*)(g_Arows + (size_t)3 * (Bn*HW) * 4);
    #pragma unroll
    for (int mt = 0; mt < 2; mt++) {
        #pragma unroll
        for (int hf = 0; hf < 2; hf++) {
            int px_local = mt*16 + gid + hf*8;
            int py = ty0 + w;
            int px = tx0 + px_local;
            size_t pidx = (size_t)b * CHW + (size_t)py * Ww + px;
            uint32_t* rp = rowbase + ((size_t)b * HW + (size_t)py * Ww + px) * 16;
            #pragma unroll
            for (int n = 0; n < 4; n++) {
                int cl = n*8 + 2*tig;
                int co = half*32 + cl;
                float a0 = acc[mt][n][hf*2]     * WINV + g_bcomb[co];
                float a1 = acc[mt][n][hf*2 + 1] * WINV + g_bcomb[co+1];
                float i0 = g_invtau[co], i1 = g_invtau[co+1];
                float c0 = fast_tanh(a0), c1 = fast_tanh(a1);
                if (half == 0) {
                    float h0 = (i0 < 1.f) ? he[pidx + (size_t)cl * HW]     : 0.f;
                    float h1 = (i1 < 1.f) ? he[pidx + (size_t)(cl+1) * HW] : 0.f;
                    float v0 = (1.f - i0)*h0 + i0*c0;
                    float v1 = (1.f - i1)*h1 + i1*c1;
                    out[(size_t)NTOT + pidx + (size_t)cl * HW]     = v0;
                    out[(size_t)NTOT + pidx + (size_t)(cl+1) * HW] = v1;
                    rp[cl >> 1] = (uint32_t)f2h(v0) | ((uint32_t)f2h(v1) << 16);
                } else {
                    float h0 = (i0 < 1.f) ? hi[pidx + (size_t)cl * HW]     : 0.f;
                    float h1 = (i1 < 1.f) ? hi[pidx + (size_t)(cl+1) * HW] : 0.f;
                    out[(size_t)2*NTOT + pidx + (size_t)cl * HW]     = (1.f - i0)*h0 + i0*c0;
                    out[(size_t)2*NTOT + pidx + (size_t)(cl+1) * HW] = (1.f - i1)*h1 + i1*c1;
                }
            }
        }
    }
}

// ---------------- out kernel ----------------
__global__ void __launch_bounds__(THREADS, 2)
out_kernel(float* __restrict__ out)
{
    extern __shared__ char sm[];
    const uint32_t smb = smem_u32(sm);
    const int tid  = threadIdx.x;
    const int w    = tid >> 5;
    const int lane = tid & 31;
    const int gid  = lane >> 2;
    const int tig  = lane & 3;
    const int b    = blockIdx.z;
    const int ty0  = blockIdx.y * 8;
    const int tx0  = blockIdx.x * 32;

    float acc[2][4][4];
    #pragma unroll
    for (int mt = 0; mt < 2; mt++)
        #pragma unroll
        for (int n = 0; n < 4; n++)
            #pragma unroll
            for (int q = 0; q < 4; q++) acc[mt][n][q] = 0.f;

    const int hbase = (w + 1) * 34 + 1;
    const uint32_t laneA0 = smb + (uint32_t)(hbase + (lane & 15)) * RS
                          + (uint32_t)((lane >> 4) << 4);

    stage_A(sm, smb, 0, 3, b, ty0, tx0, tid);
    CP_COMMIT();
    CP_WAIT0();
    __syncthreads();

    const uint4* Bp = g_BfragOut + lane;
    conv_tap_loop(acc, laneA0, laneA0 + 16u*RS, Bp);

    #pragma unroll
    for (int mt = 0; mt < 2; mt++) {
        #pragma unroll
        for (int hf = 0; hf < 2; hf++) {
            int px_local = mt*16 + gid + hf*8;
            int py = ty0 + w;
            int px = tx0 + px_local;
            size_t pidx = (size_t)b * CHW + (size_t)py * Ww + px;
            #pragma unroll
            for (int n = 0; n < 4; n++) {
                #pragma unroll
                for (int q = 0; q < 2; q++) {
                    int co  = n*8 + 2*tig + q;
                    float v = acc[mt][n][hf*2 + q] * WINV + g_bout[co];
                    out[pidx + (size_t)co * HW] = fast_tanh(v);
                }
            }
        }
    }
}

extern "C" void kernel_launch(void* const* d_in, const int* in_sizes, int n_in,
                              void* d_out, int out_size)
{
    (void)in_sizes; (void)n_in; (void)out_size;
    const float* x  = (const float*)d_in[0];
    const float* he = (const float*)d_in[1];
    const float* hi = (const float*)d_in[2];
    float* out = (float*)d_out;

    cudaFuncSetAttribute(state_kernel, cudaFuncAttributeMaxDynamicSharedMemorySize, SMEM_T);
    cudaFuncSetAttribute(out_kernel,   cudaFuncAttributeMaxDynamicSharedMemorySize, A_SZ);

    prep_kernel<<<63, 256>>>(
        (const float*)d_in[3],  (const float*)d_in[4],
        (const float*)d_in[5],  (const float*)d_in[6],
        (const float*)d_in[7],  (const float*)d_in[8],
        (const float*)d_in[9],  (const float*)d_in[10],
        (const float*)d_in[11], (const float*)d_in[12],
        (const float*)d_in[13], (const float*)d_in[14],
        (const float*)d_in[15], (const float*)d_in[16],
        (const float*)d_in[17], (const float*)d_in[18]);

    convert_kernel<<<(3*Bn*HW)/256, 256>>>(x, he, hi);

    dim3 gs(4, 16, Bn*2);   // x-tiles, y-tiles, batch x co-half
    state_kernel<<<gs, THREADS, SMEM_T>>>(he, hi, out);
    dim3 go(4, 16, Bn);
    out_kernel<<<go, THREADS, A_SZ>>>(out);
}

// round 15
// speedup vs baseline: 1.5987x; 1.0082x over previous
#include <cuda_runtime.h>
#include <math.h>
#include <stdint.h>

#define Bn 16
#define Cc 32
#define Hh 128
#define Ww 128
#define HW (Hh*Ww)
#define CHW (Cc*HW)
#define NTOT (Bn*CHW)

// block tile: 8 out rows x 32 out cols = 256 px; halo 10x34 = 340 A rows
#define THREADS 256
#define NROWS 340

#define RS     80                     // SMEM row stride: 64B fp16 data + 16 pad
#define A_SZ   (NROWS*RS)             // 27200 bytes per buffer
#define SMEM_T (2*A_SZ)               // 54400: double-buffered A

#define WSCL   2048.0f
#define WINV   (1.0f/2048.0f)

// global A-row images: [t(4)][b*HW + pix] rows of 64B (32ci fp16), dense
__device__ uint4 g_Arows[(size_t)4*Bn*HW*4];

// B fragment tables, register-image order:
// state: [t(3)][half(2)][tap(9)][plane(2)][s(2)][p(2)][lane(32)] -> 13824 uint4
// out:   [tap(9)][plane(2)][s(2)][p(2)][lane(32)]                -> 2304 uint4
#define STFRAG (3*2*9*2*2*2*32)
#define OUTFRAG (9*2*2*2*32)
__device__ __align__(16) uint4 g_BfragSt[STFRAG];
__device__ __align__(16) uint4 g_BfragOut[OUTFRAG];
__device__ float g_bcomb[64];
__device__ float g_bout[32];
__device__ float g_invtau[64];

// ---------------- helpers ----------------
__device__ __forceinline__ uint32_t smem_u32(const void* p) {
    uint32_t a;
    asm("{ .reg .u64 t; cvta.to.shared.u64 t, %1; cvt.u32.u64 %0, t; }" : "=r"(a) : "l"(p));
    return a;
}
__device__ __forceinline__ unsigned short f2h(float v) {
    unsigned short h;
    asm("cvt.rn.f16.f32 %0, %1;" : "=h"(h) : "f"(v));
    return h;
}
__device__ __forceinline__ float h2f(unsigned short h) {
    float f;
    asm("cvt.f32.f16 %0, %1;" : "=f"(f) : "h"(h));
    return f;
}
__device__ __forceinline__ float fast_tanh(float x) {
    float e, r;
    asm("ex2.approx.f32 %0, %1;" : "=f"(e) : "f"(x * 2.8853900817779268f));
    asm("rcp.approx.f32 %0, %1;" : "=f"(r) : "f"(e + 1.f));
    return fmaf(-2.f, r, 1.f);
}
__device__ __forceinline__ void mma16816(float* c,
    uint32_t a0, uint32_t a1, uint32_t a2, uint32_t a3, uint32_t b0, uint32_t b1)
{
    asm volatile(
        "mma.sync.aligned.m16n8k16.row.col.f32.f16.f16.f32 "
        "{%0,%1,%2,%3}, {%4,%5,%6,%7}, {%8,%9}, {%0,%1,%2,%3};"
        : "+f"(c[0]), "+f"(c[1]), "+f"(c[2]), "+f"(c[3])
        : "r"(a0), "r"(a1), "r"(a2), "r"(a3), "r"(b0), "r"(b1));
}
__device__ __forceinline__ void ldsm4(uint32_t* r, uint32_t addr) {
    asm volatile("ldmatrix.sync.aligned.m8n8.x4.shared.b16 {%0,%1,%2,%3}, [%4];"
        : "=r"(r[0]), "=r"(r[1]), "=r"(r[2]), "=r"(r[3]) : "r"(addr));
}
__device__ __forceinline__ void cp16(uint32_t smdst, const void* gsrc) {
    asm volatile("cp.async.cg.shared.global [%0], [%1], 16;" :: "r"(smdst), "l"(gsrc));
}
#define CP_COMMIT() asm volatile("cp.async.commit_group;" ::: "memory")
#define CP_WAIT0()  asm volatile("cp.async.wait_group 0;" ::: "memory")
#define CP_WAIT1()  asm volatile("cp.async.wait_group 1;" ::: "memory")

// ---------------- prep: Dale fold, x2048 scale, fp16 hi/lo split, FRAGMENT order ----------------
__global__ void prep_kernel(
    const float* __restrict__ W_in_e, const float* __restrict__ b_in_e,
    const float* __restrict__ W_in_i, const float* __restrict__ b_in_i,
    const float* __restrict__ W_e_e,  const float* __restrict__ b_e_e,
    const float* __restrict__ W_e_i,  const float* __restrict__ b_e_i,
    const float* __restrict__ W_e_out,const float* __restrict__ b_e_out,
    const float* __restrict__ W_i_e,  const float* __restrict__ b_i_e,
    const float* __restrict__ W_i_i,  const float* __restrict__ b_i_i,
    const float* __restrict__ tau_e,  const float* __restrict__ tau_i)
{
    int fid = blockIdx.x * 256 + threadIdx.x;
    if (fid < STFRAG) {
        int lane = fid & 31;
        int q    = fid >> 5;
        int p     = q & 1;  q >>= 1;
        int s     = q & 1;  q >>= 1;
        int plane = q & 1;  q >>= 1;
        int tap   = q % 9;  q /= 9;
        int half  = q & 1;
        int t     = q >> 1;
        uint32_t comp[4];
        #pragma unroll
        for (int j = 0; j < 4; j++) {
            int co_l = p*16 + ((j>>1)<<3) + (lane>>2);
            int ci   = s*16 + ((j&1)<<3) + ((lane&3)<<1);
            unsigned short v[2];
            #pragma unroll
            for (int e = 0; e < 2; e++) {
                int src = co_l * 288 + (ci + e) * 9 + tap;   // OIHW
                float w;
                if (t == 0)      w = (half == 0) ? W_in_e[src] : W_in_i[src];
                else if (t == 1) w = fmaxf((half == 0) ? W_e_e[src] : W_e_i[src], 0.f);
                else             w = -fmaxf((half == 0) ? W_i_e[src] : W_i_i[src], 0.f);
                w *= WSCL;
                unsigned short hh = f2h(w);
                v[e] = plane ? f2h(w - h2f(hh)) : hh;
            }
            comp[j] = (uint32_t)v[0] | ((uint32_t)v[1] << 16);
        }
        g_BfragSt[fid] = make_uint4(comp[0], comp[1], comp[2], comp[3]);
    } else if (fid < STFRAG + OUTFRAG) {
        int f2   = fid - STFRAG;
        int lane = f2 & 31;
        int q    = f2 >> 5;
        int p     = q & 1;  q >>= 1;
        int s     = q & 1;  q >>= 1;
        int plane = q & 1;  q >>= 1;
        int tap   = q;
        uint32_t comp[4];
        #pragma unroll
        for (int j = 0; j < 4; j++) {
            int co_l = p*16 + ((j>>1)<<3) + (lane>>2);
            int ci   = s*16 + ((j&1)<<3) + ((lane&3)<<1);
            unsigned short v[2];
            #pragma unroll
            for (int e = 0; e < 2; e++) {
                float w = fmaxf(W_e_out[co_l*288 + (ci + e)*9 + tap], 0.f) * WSCL;
                unsigned short hh = f2h(w);
                v[e] = plane ? f2h(w - h2f(hh)) : hh;
            }
            comp[j] = (uint32_t)v[0] | ((uint32_t)v[1] << 16);
        }
        g_BfragOut[f2] = make_uint4(comp[0], comp[1], comp[2], comp[3]);
    }
    if (blockIdx.x == 0 && threadIdx.x < 64) {
        int co = threadIdx.x;
        if (co < 32) {
            g_bcomb[co]  = b_in_e[co] + fmaxf(b_e_e[co], 0.f) - fmaxf(b_i_e[co], 0.f);
            g_invtau[co] = 1.f / fmaxf(tau_e[co], 1.f);
            g_bout[co]   = fmaxf(b_e_out[co], 0.f);
        } else {
            int c = co - 32;
            g_bcomb[co]  = b_in_i[c] + fmaxf(b_e_i[c], 0.f) - fmaxf(b_i_i[c], 0.f);
            g_invtau[co] = 1.f / fmaxf(tau_i[c], 1.f);
        }
    }
}

// ---------------- convert: NCHW fp32 -> per-pixel 64B fp16 rows ----------------
__global__ void __launch_bounds__(256)
convert_kernel(const float* __restrict__ x, const float* __restrict__ he,
               const float* __restrict__ hi)
{
    int gidx = blockIdx.x * 256 + threadIdx.x;
    int t = gidx / (Bn*HW);
    int p = gidx - t * (Bn*HW);
    int b = p / HW;
    int pix = p - b * HW;
    const float* src = (t == 0 ? x : (t == 1 ? he : hi)) + (size_t)b * CHW + pix;
    uint4* dst = g_Arows + ((size_t)t * (Bn*HW) + p) * 4;

    uint32_t hw[16];
    #pragma unroll
    for (int k = 0; k < 16; k++) {
        unsigned short h0 = f2h(src[(size_t)(2*k)   * HW]);
        unsigned short h1 = f2h(src[(size_t)(2*k+1) * HW]);
        hw[k] = (uint32_t)h0 | ((uint32_t)h1 << 16);
    }
    #pragma unroll
    for (int j = 0; j < 4; j++)
        dst[j] = make_uint4(hw[4*j], hw[4*j+1], hw[4*j+2], hw[4*j+3]);
}

// ---------------- A tile staging: 64B rows, division-free ----------------
__device__ __forceinline__ void stage_A(char* sm, uint32_t smb, uint32_t a_off,
                                        int t, int b, int ty0, int tx0, int tid)
{
    const char* gb = (const char*)g_Arows + ((size_t)t * (Bn*HW) + (size_t)b * HW) * 64;
    const int c   = tid & 3;
    const int col = tid >> 2;
    if (col >= 34) return;

    const int gx   = tx0 + col - 1;
    const bool okx = ((unsigned)gx < 128u);
    uint32_t dst = smb + a_off + (uint32_t)col * RS + (uint32_t)c * 16;
    const char* src = gb + ((size_t)(ty0 - 1) * Ww + gx) * 64 + c * 16;

    #pragma unroll
    for (int ry = 0; ry < 10; ry++) {
        const int gy = ty0 + ry - 1;
        if (((unsigned)gy < 128u) && okx) cp16(dst, src);
        else                              *(uint4*)(sm + (dst - smb)) = make_uint4(0,0,0,0);
        dst += 34u * RS;
        src += (size_t)Ww * 64;
    }
}

// load a tap's 8 B fragments (flat reg image: [g(plane*4+s*2+p)][4])
__device__ __forceinline__ void load_B(const uint4* __restrict__ bp, uint32_t* bf) {
    #pragma unroll
    for (int g = 0; g < 8; g++) {
        uint4 qv = bp[(size_t)g * 32];
        bf[g*4+0] = qv.x; bf[g*4+1] = qv.y; bf[g*4+2] = qv.z; bf[g*4+3] = qv.w;
    }
}

// ---------------- mainloop: 2-pass fp16, fully unrolled, B reg-pipelined,
// MMAs interleaved by pass so each accumulator's RAW distance is 8 MMAs ----------------
__device__ __forceinline__ void conv_tap_loop(
    float acc[2][4][4], const uint32_t laneA0, const uint32_t laneA1,
    const uint4* __restrict__ Bp)
{
    uint32_t B[2][32];
    load_B(Bp, B[0]);

    #pragma unroll
    for (int tap = 0; tap < 9; tap++) {
        // prefetch next tap's B fragments (latency hidden behind this tap's MMAs)
        if (tap < 8) load_B(Bp + (size_t)(tap + 1) * 256, B[(tap + 1) & 1]);

        const int soff = ((tap/3) - 1) * (34*RS) + ((tap % 3) - 1) * RS;
        uint32_t Aa[2][2][4];
        ldsm4(Aa[0][0], laneA0 + soff + 0);  ldsm4(Aa[0][1], laneA0 + soff + 32);
        ldsm4(Aa[1][0], laneA1 + soff + 0);  ldsm4(Aa[1][1], laneA1 + soff + 32);

        const uint32_t* bc = B[tap & 1];
        // pass order: (s, plane); inner (mt, n) touches 8 distinct accumulators
        #pragma unroll
        for (int s = 0; s < 2; s++) {
            #pragma unroll
            for (int pl = 0; pl < 2; pl++) {
                const uint32_t* bb = bc + pl*16 + s*8;   // [p(2)][4]
                #pragma unroll
                for (int mt = 0; mt < 2; mt++)
                    #pragma unroll
                    for (int n = 0; n < 4; n++) {
                        const int p = n >> 1, q = (n & 1) * 2;
                        mma16816(acc[mt][n],
                                 Aa[mt][s][0], Aa[mt][s][1], Aa[mt][s][2], Aa[mt][s][3],
                                 bb[p*4 + q], bb[p*4 + q + 1]);
                    }
            }
        }
    }
}

// ---------------- state kernel (N-split; double-buffered A pipeline) ----------------
__global__ void __launch_bounds__(THREADS, 2)
state_kernel(const float* __restrict__ he, const float* __restrict__ hi,
             float* __restrict__ out)
{
    extern __shared__ char sm[];
    const uint32_t smb = smem_u32(sm);
    const int tid  = threadIdx.x;
    const int w    = tid >> 5;
    const int lane = tid & 31;
    const int gid  = lane >> 2;
    const int tig  = lane & 3;
    const int b    = blockIdx.z >> 1;
    const int half = blockIdx.z & 1;
    const int ty0  = blockIdx.y * 8;
    const int tx0  = blockIdx.x * 32;

    float acc[2][4][4];
    #pragma unroll
    for (int mt = 0; mt < 2; mt++)
        #pragma unroll
        for (int n = 0; n < 4; n++)
            #pragma unroll
            for (int q = 0; q < 4; q++) acc[mt][n][q] = 0.f;

    const int hbase = (w + 1) * 34 + 1;
    const uint32_t laneA0b = smb + (uint32_t)(hbase + (lane & 15)) * RS
                           + (uint32_t)((lane >> 4) << 4);

    stage_A(sm, smb, 0, 0, b, ty0, tx0, tid);
    CP_COMMIT();

    #pragma unroll 1
    for (int t = 0; t < 3; t++) {
        if (t < 2) {
            stage_A(sm, smb, (uint32_t)((t + 1) & 1) * A_SZ, t + 1, b, ty0, tx0, tid);
            CP_COMMIT();
            CP_WAIT1();
        } else {
            CP_WAIT0();
        }
        __syncthreads();

        const uint32_t laneA0 = laneA0b + (uint32_t)(t & 1) * A_SZ;
        const uint4* Bp = g_BfragSt + ((size_t)(t*2 + half) * 9) * 256 + lane;
        conv_tap_loop(acc, laneA0, laneA0 + 16u*RS, Bp);
        __syncthreads();
    }

    // epilogue: unscale, bias, tanh, leaky integrate; emit h_e_new fp16 rows
    uint32_t* rowbase = (uint32_t*)(g_Arows + (size_t)3 * (Bn*HW) * 4);
    #pragma unroll
    for (int mt = 0; mt < 2; mt++) {
        #pragma unroll
        for (int hf = 0; hf < 2; hf++) {
            int px_local = mt*16 + gid + hf*8;
            int py = ty0 + w;
            int px = tx0 + px_local;
            size_t pidx = (size_t)b * CHW + (size_t)py * Ww + px;
            uint32_t* rp = rowbase + ((size_t)b * HW + (size_t)py * Ww + px) * 16;
            #pragma unroll
            for (int n = 0; n < 4; n++) {
                int cl = n*8 + 2*tig;
                int co = half*32 + cl;
                float a0 = acc[mt][n][hf*2]     * WINV + g_bcomb[co];
                float a1 = acc[mt][n][hf*2 + 1] * WINV + g_bcomb[co+1];
                float i0 = g_invtau[co], i1 = g_invtau[co+1];
                float c0 = fast_tanh(a0), c1 = fast_tanh(a1);
                if (half == 0) {
                    float h0 = (i0 < 1.f) ? he[pidx + (size_t)cl * HW]     : 0.f;
                    float h1 = (i1 < 1.f) ? he[pidx + (size_t)(cl+1) * HW] : 0.f;
                    float v0 = (1.f - i0)*h0 + i0*c0;
                    float v1 = (1.f - i1)*h1 + i1*c1;
                    out[(size_t)NTOT + pidx + (size_t)cl * HW]     = v0;
                    out[(size_t)NTOT + pidx + (size_t)(cl+1) * HW] = v1;
                    rp[cl >> 1] = (uint32_t)f2h(v0) | ((uint32_t)f2h(v1) << 16);
                } else {
                    float h0 = (i0 < 1.f) ? hi[pidx + (size_t)cl * HW]     : 0.f;
                    float h1 = (i1 < 1.f) ? hi[pidx + (size_t)(cl+1) * HW] : 0.f;
                    out[(size_t)2*NTOT + pidx + (size_t)cl * HW]     = (1.f - i0)*h0 + i0*c0;
                    out[(size_t)2*NTOT + pidx + (size_t)(cl+1) * HW] = (1.f - i1)*h1 + i1*c1;
                }
            }
        }
    }
}

// ---------------- out kernel ----------------
__global__ void __launch_bounds__(THREADS, 2)
out_kernel(float* __restrict__ out)
{
    extern __shared__ char sm[];
    const uint32_t smb = smem_u32(sm);
    const int tid  = threadIdx.x;
    const int w    = tid >> 5;
    const int lane = tid & 31;
    const int gid  = lane >> 2;
    const int tig  = lane & 3;
    const int b    = blockIdx.z;
    const int ty0  = blockIdx.y * 8;
    const int tx0  = blockIdx.x * 32;

    float acc[2][4][4];
    #pragma unroll
    for (int mt = 0; mt < 2; mt++)
        #pragma unroll
        for (int n = 0; n < 4; n++)
            #pragma unroll
            for (int q = 0; q < 4; q++) acc[mt][n][q] = 0.f;

    const int hbase = (w + 1) * 34 + 1;
    const uint32_t laneA0 = smb + (uint32_t)(hbase + (lane & 15)) * RS
                          + (uint32_t)((lane >> 4) << 4);

    stage_A(sm, smb, 0, 3, b, ty0, tx0, tid);
    CP_COMMIT();
    CP_WAIT0();
    __syncthreads();

    const uint4* Bp = g_BfragOut + lane;
    conv_tap_loop(acc, laneA0, laneA0 + 16u*RS, Bp);

    #pragma unroll
    for (int mt = 0; mt < 2; mt++) {
        #pragma unroll
        for (int hf = 0; hf < 2; hf++) {
            int px_local = mt*16 + gid + hf*8;
            int py = ty0 + w;
            int px = tx0 + px_local;
            size_t pidx = (size_t)b * CHW + (size_t)py * Ww + px;
            #pragma unroll
            for (int n = 0; n < 4; n++) {
                #pragma unroll
                for (int q = 0; q < 2; q++) {
                    int co  = n*8 + 2*tig + q;
                    float v = acc[mt][n][hf*2 + q] * WINV + g_bout[co];
                    out[pidx + (size_t)co * HW] = fast_tanh(v);
                }
            }
        }
    }
}

extern "C" void kernel_launch(void* const* d_in, const int* in_sizes, int n_in,
                              void* d_out, int out_size)
{
    (void)in_sizes; (void)n_in; (void)out_size;
    const float* x  = (const float*)d_in[0];
    const float* he = (const float*)d_in[1];
    const float* hi = (const float*)d_in[2];
    float* out = (float*)d_out;

    cudaFuncSetAttribute(state_kernel, cudaFuncAttributeMaxDynamicSharedMemorySize, SMEM_T);
    cudaFuncSetAttribute(out_kernel,   cudaFuncAttributeMaxDynamicSharedMemorySize, A_SZ);

    prep_kernel<<<63, 256>>>(
        (const float*)d_in[3],  (const float*)d_in[4],
        (const float*)d_in[5],  (const float*)d_in[6],
        (const float*)d_in[7],  (const float*)d_in[8],
        (const float*)d_in[9],  (const float*)d_in[10],
        (const float*)d_in[11], (const float*)d_in[12],
        (const float*)d_in[13], (const float*)d_in[14],
        (const float*)d_in[15], (const float*)d_in[16],
        (const float*)d_in[17], (const float*)d_in[18]);

    convert_kernel<<<(3*Bn*HW)/256, 256>>>(x, he, hi);

    dim3 gs(4, 16, Bn*2);   // x-tiles, y-tiles, batch x co-half
    state_kernel<<<gs, THREADS, SMEM_T>>>(he, hi, out);
    dim3 go(4, 16, Bn);
    out_kernel<<<go, THREADS, A_SZ>>>(out);
}

// round 16
// speedup vs baseline: 2.0726x; 1.2964x over previous
#include <cuda_runtime.h>
#include <math.h>
#include <stdint.h>

#define Bn 16
#define Cc 32
#define Hh 128
#define Ww 128
#define HW (Hh*Ww)
#define CHW (Cc*HW)
#define NTOT (Bn*CHW)

// block tile: 8 out rows x 32 out cols = 256 px; halo 10x34 = 340 A rows
#define THREADS 256
#define NROWS 340

#define RS     80                     // SMEM row stride: 64B fp16 data + 16 pad
#define A_SZ   (NROWS*RS)             // 27200 bytes per buffer
#define SMEM_T (2*A_SZ)               // 54400: double-buffered A

// global A-row images: [t(4)][b*HW + pix] rows of 64B (32ci fp16), dense
__device__ uint4 g_Arows[(size_t)4*Bn*HW*4];

// B fragment tables (single fp16 plane), register-image order:
// state: [t(3)][half(2)][tap(9)][s(2)][p(2)][lane(32)] -> 6912 uint4
// out:   [tap(9)][s(2)][p(2)][lane(32)]                -> 1152 uint4
#define STFRAG (3*2*9*2*2*32)
#define OUTFRAG (9*2*2*32)
__device__ __align__(16) uint4 g_BfragSt[STFRAG];
__device__ __align__(16) uint4 g_BfragOut[OUTFRAG];
__device__ float g_bcomb[64];
__device__ float g_bout[32];
__device__ float g_invtau[64];

// ---------------- helpers ----------------
__device__ __forceinline__ uint32_t smem_u32(const void* p) {
    uint32_t a;
    asm("{ .reg .u64 t; cvta.to.shared.u64 t, %1; cvt.u32.u64 %0, t; }" : "=r"(a) : "l"(p));
    return a;
}
__device__ __forceinline__ unsigned short f2h(float v) {
    unsigned short h;
    asm("cvt.rn.f16.f32 %0, %1;" : "=h"(h) : "f"(v));
    return h;
}
__device__ __forceinline__ float fast_tanh(float x) {
    float e, r;
    asm("ex2.approx.f32 %0, %1;" : "=f"(e) : "f"(x * 2.8853900817779268f));
    asm("rcp.approx.f32 %0, %1;" : "=f"(r) : "f"(e + 1.f));
    return fmaf(-2.f, r, 1.f);
}
__device__ __forceinline__ void mma16816(float* c,
    uint32_t a0, uint32_t a1, uint32_t a2, uint32_t a3, uint32_t b0, uint32_t b1)
{
    asm volatile(
        "mma.sync.aligned.m16n8k16.row.col.f32.f16.f16.f32 "
        "{%0,%1,%2,%3}, {%4,%5,%6,%7}, {%8,%9}, {%0,%1,%2,%3};"
        : "+f"(c[0]), "+f"(c[1]), "+f"(c[2]), "+f"(c[3])
        : "r"(a0), "r"(a1), "r"(a2), "r"(a3), "r"(b0), "r"(b1));
}
__device__ __forceinline__ void ldsm4(uint32_t* r, uint32_t addr) {
    asm volatile("ldmatrix.sync.aligned.m8n8.x4.shared.b16 {%0,%1,%2,%3}, [%4];"
        : "=r"(r[0]), "=r"(r[1]), "=r"(r[2]), "=r"(r[3]) : "r"(addr));
}
__device__ __forceinline__ void cp16(uint32_t smdst, const void* gsrc) {
    asm volatile("cp.async.cg.shared.global [%0], [%1], 16;" :: "r"(smdst), "l"(gsrc));
}
#define CP_COMMIT() asm volatile("cp.async.commit_group;" ::: "memory")
#define CP_WAIT0()  asm volatile("cp.async.wait_group 0;" ::: "memory")
#define CP_WAIT1()  asm volatile("cp.async.wait_group 1;" ::: "memory")

// ---------------- prep: Dale fold, plain fp16 weights, FRAGMENT order ----------------
__global__ void prep_kernel(
    const float* __restrict__ W_in_e, const float* __restrict__ b_in_e,
    const float* __restrict__ W_in_i, const float* __restrict__ b_in_i,
    const float* __restrict__ W_e_e,  const float* __restrict__ b_e_e,
    const float* __restrict__ W_e_i,  const float* __restrict__ b_e_i,
    const float* __restrict__ W_e_out,const float* __restrict__ b_e_out,
    const float* __restrict__ W_i_e,  const float* __restrict__ b_i_e,
    const float* __restrict__ W_i_i,  const float* __restrict__ b_i_i,
    const float* __restrict__ tau_e,  const float* __restrict__ tau_i)
{
    int fid = blockIdx.x * 256 + threadIdx.x;
    if (fid < STFRAG) {
        int lane = fid & 31;
        int q    = fid >> 5;
        int p     = q & 1;  q >>= 1;
        int s     = q & 1;  q >>= 1;
        int tap   = q % 9;  q /= 9;
        int half  = q & 1;
        int t     = q >> 1;
        uint32_t comp[4];
        #pragma unroll
        for (int j = 0; j < 4; j++) {
            int co_l = p*16 + ((j>>1)<<3) + (lane>>2);
            int ci   = s*16 + ((j&1)<<3) + ((lane&3)<<1);
            unsigned short v[2];
            #pragma unroll
            for (int e = 0; e < 2; e++) {
                int src = co_l * 288 + (ci + e) * 9 + tap;   // OIHW
                float w;
                if (t == 0)      w = (half == 0) ? W_in_e[src] : W_in_i[src];
                else if (t == 1) w = fmaxf((half == 0) ? W_e_e[src] : W_e_i[src], 0.f);
                else             w = -fmaxf((half == 0) ? W_i_e[src] : W_i_i[src], 0.f);
                v[e] = f2h(w);
            }
            comp[j] = (uint32_t)v[0] | ((uint32_t)v[1] << 16);
        }
        g_BfragSt[fid] = make_uint4(comp[0], comp[1], comp[2], comp[3]);
    } else if (fid < STFRAG + OUTFRAG) {
        int f2   = fid - STFRAG;
        int lane = f2 & 31;
        int q    = f2 >> 5;
        int p     = q & 1;  q >>= 1;
        int s     = q & 1;  q >>= 1;
        int tap   = q;
        uint32_t comp[4];
        #pragma unroll
        for (int j = 0; j < 4; j++) {
            int co_l = p*16 + ((j>>1)<<3) + (lane>>2);
            int ci   = s*16 + ((j&1)<<3) + ((lane&3)<<1);
            unsigned short v[2];
            #pragma unroll
            for (int e = 0; e < 2; e++)
                v[e] = f2h(fmaxf(W_e_out[co_l*288 + (ci + e)*9 + tap], 0.f));
            comp[j] = (uint32_t)v[0] | ((uint32_t)v[1] << 16);
        }
        g_BfragOut[f2] = make_uint4(comp[0], comp[1], comp[2], comp[3]);
    }
    if (blockIdx.x == 0 && threadIdx.x < 64) {
        int co = threadIdx.x;
        if (co < 32) {
            g_bcomb[co]  = b_in_e[co] + fmaxf(b_e_e[co], 0.f) - fmaxf(b_i_e[co], 0.f);
            g_invtau[co] = 1.f / fmaxf(tau_e[co], 1.f);
            g_bout[co]   = fmaxf(b_e_out[co], 0.f);
        } else {
            int c = co - 32;
            g_bcomb[co]  = b_in_i[c] + fmaxf(b_e_i[c], 0.f) - fmaxf(b_i_i[c], 0.f);
            g_invtau[co] = 1.f / fmaxf(tau_i[c], 1.f);
        }
    }
}

// ---------------- convert: NCHW fp32 -> per-pixel 64B fp16 rows ----------------
__global__ void __launch_bounds__(256)
convert_kernel(const float* __restrict__ x, const float* __restrict__ he,
               const float* __restrict__ hi)
{
    int gidx = blockIdx.x * 256 + threadIdx.x;
    int t = gidx / (Bn*HW);
    int p = gidx - t * (Bn*HW);
    int b = p / HW;
    int pix = p - b * HW;
    const float* src = (t == 0 ? x : (t == 1 ? he : hi)) + (size_t)b * CHW + pix;
    uint4* dst = g_Arows + ((size_t)t * (Bn*HW) + p) * 4;

    uint32_t hw[16];
    #pragma unroll
    for (int k = 0; k < 16; k++) {
        unsigned short h0 = f2h(src[(size_t)(2*k)   * HW]);
        unsigned short h1 = f2h(src[(size_t)(2*k+1) * HW]);
        hw[k] = (uint32_t)h0 | ((uint32_t)h1 << 16);
    }
    #pragma unroll
    for (int j = 0; j < 4; j++)
        dst[j] = make_uint4(hw[4*j], hw[4*j+1], hw[4*j+2], hw[4*j+3]);
}

// ---------------- A tile staging: 64B rows, division-free ----------------
__device__ __forceinline__ void stage_A(char* sm, uint32_t smb, uint32_t a_off,
                                        int t, int b, int ty0, int tx0, int tid)
{
    const char* gb = (const char*)g_Arows + ((size_t)t * (Bn*HW) + (size_t)b * HW) * 64;
    const int c   = tid & 3;
    const int col = tid >> 2;
    if (col >= 34) return;

    const int gx   = tx0 + col - 1;
    const bool okx = ((unsigned)gx < 128u);
    uint32_t dst = smb + a_off + (uint32_t)col * RS + (uint32_t)c * 16;
    const char* src = gb + ((size_t)(ty0 - 1) * Ww + gx) * 64 + c * 16;

    #pragma unroll
    for (int ry = 0; ry < 10; ry++) {
        const int gy = ty0 + ry - 1;
        if (((unsigned)gy < 128u) && okx) cp16(dst, src);
        else                              *(uint4*)(sm + (dst - smb)) = make_uint4(0,0,0,0);
        dst += 34u * RS;
        src += (size_t)Ww * 64;
    }
}

// load a tap's 4 B fragments (flat reg image: [g(s*2+p)][4])
__device__ __forceinline__ void load_B(const uint4* __restrict__ bp, uint32_t* bf) {
    #pragma unroll
    for (int g = 0; g < 4; g++) {
        uint4 qv = bp[(size_t)g * 32];
        bf[g*4+0] = qv.x; bf[g*4+1] = qv.y; bf[g*4+2] = qv.z; bf[g*4+3] = qv.w;
    }
}

// ---------------- mainloop: single-pass fp16, fully unrolled, B reg-pipelined ----------------
__device__ __forceinline__ void conv_tap_loop(
    float acc[2][4][4], const uint32_t laneA0, const uint32_t laneA1,
    const uint4* __restrict__ Bp)
{
    uint32_t B[2][16];
    load_B(Bp, B[0]);

    #pragma unroll
    for (int tap = 0; tap < 9; tap++) {
        if (tap < 8) load_B(Bp + (size_t)(tap + 1) * 128, B[(tap + 1) & 1]);

        const int soff = ((tap/3) - 1) * (34*RS) + ((tap % 3) - 1) * RS;
        uint32_t Aa[2][2][4];
        ldsm4(Aa[0][0], laneA0 + soff + 0);  ldsm4(Aa[0][1], laneA0 + soff + 32);
        ldsm4(Aa[1][0], laneA1 + soff + 0);  ldsm4(Aa[1][1], laneA1 + soff + 32);

        const uint32_t* bc = B[tap & 1];
        #pragma unroll
        for (int s = 0; s < 2; s++) {
            const uint32_t* bb = bc + s*8;   // [p(2)][4]
            #pragma unroll
            for (int mt = 0; mt < 2; mt++)
                #pragma unroll
                for (int n = 0; n < 4; n++) {
                    const int p = n >> 1, q = (n & 1) * 2;
                    mma16816(acc[mt][n],
                             Aa[mt][s][0], Aa[mt][s][1], Aa[mt][s][2], Aa[mt][s][3],
                             bb[p*4 + q], bb[p*4 + q + 1]);
                }
        }
    }
}

// ---------------- state kernel (N-split; double-buffered A pipeline) ----------------
__global__ void __launch_bounds__(THREADS, 2)
state_kernel(const float* __restrict__ he, const float* __restrict__ hi,
             float* __restrict__ out)
{
    extern __shared__ char sm[];
    const uint32_t smb = smem_u32(sm);
    const int tid  = threadIdx.x;
    const int w    = tid >> 5;
    const int lane = tid & 31;
    const int gid  = lane >> 2;
    const int tig  = lane & 3;
    const int b    = blockIdx.z >> 1;
    const int half = blockIdx.z & 1;
    const int ty0  = blockIdx.y * 8;
    const int tx0  = blockIdx.x * 32;

    float acc[2][4][4];
    #pragma unroll
    for (int mt = 0; mt < 2; mt++)
        #pragma unroll
        for (int n = 0; n < 4; n++)
            #pragma unroll
            for (int q = 0; q < 4; q++) acc[mt][n][q] = 0.f;

    const int hbase = (w + 1) * 34 + 1;
    const uint32_t laneA0b = smb + (uint32_t)(hbase + (lane & 15)) * RS
                           + (uint32_t)((lane >> 4) << 4);

    stage_A(sm, smb, 0, 0, b, ty0, tx0, tid);
    CP_COMMIT();

    #pragma unroll 1
    for (int t = 0; t < 3; t++) {
        if (t < 2) {
            stage_A(sm, smb, (uint32_t)((t + 1) & 1) * A_SZ, t + 1, b, ty0, tx0, tid);
            CP_COMMIT();
            CP_WAIT1();
        } else {
            CP_WAIT0();
        }
        __syncthreads();

        const uint32_t laneA0 = laneA0b + (uint32_t)(t & 1) * A_SZ;
        const uint4* Bp = g_BfragSt + ((size_t)(t*2 + half) * 9) * 128 + lane;
        conv_tap_loop(acc, laneA0, laneA0 + 16u*RS, Bp);
        __syncthreads();
    }

    // epilogue: bias, tanh, leaky integrate; emit h_e_new fp16 rows
    uint32_t* rowbase = (uint32_t*)(g_Arows + (size_t)3 * (Bn*HW) * 4);
    #pragma unroll
    for (int mt = 0; mt < 2; mt++) {
        #pragma unroll
        for (int hf = 0; hf < 2; hf++) {
            int px_local = mt*16 + gid + hf*8;
            int py = ty0 + w;
            int px = tx0 + px_local;
            size_t pidx = (size_t)b * CHW + (size_t)py * Ww + px;
            uint32_t* rp = rowbase + ((size_t)b * HW + (size_t)py * Ww + px) * 16;
            #pragma unroll
            for (int n = 0; n < 4; n++) {
                int cl = n*8 + 2*tig;
                int co = half*32 + cl;
                float a0 = acc[mt][n][hf*2]     + g_bcomb[co];
                float a1 = acc[mt][n][hf*2 + 1] + g_bcomb[co+1];
                float i0 = g_invtau[co], i1 = g_invtau[co+1];
                float c0 = fast_tanh(a0), c1 = fast_tanh(a1);
                if (half == 0) {
                    float h0 = (i0 < 1.f) ? he[pidx + (size_t)cl * HW]     : 0.f;
                    float h1 = (i1 < 1.f) ? he[pidx + (size_t)(cl+1) * HW] : 0.f;
                    float v0 = (1.f - i0)*h0 + i0*c0;
                    float v1 = (1.f - i1)*h1 + i1*c1;
                    out[(size_t)NTOT + pidx + (size_t)cl * HW]     = v0;
                    out[(size_t)NTOT + pidx + (size_t)(cl+1) * HW] = v1;
                    rp[cl >> 1] = (uint32_t)f2h(v0) | ((uint32_t)f2h(v1) << 16);
                } else {
                    float h0 = (i0 < 1.f) ? hi[pidx + (size_t)cl * HW]     : 0.f;
                    float h1 = (i1 < 1.f) ? hi[pidx + (size_t)(cl+1) * HW] : 0.f;
                    out[(size_t)2*NTOT + pidx + (size_t)cl * HW]     = (1.f - i0)*h0 + i0*c0;
                    out[(size_t)2*NTOT + pidx + (size_t)(cl+1) * HW] = (1.f - i1)*h1 + i1*c1;
                }
            }
        }
    }
}

// ---------------- out kernel ----------------
__global__ void __launch_bounds__(THREADS, 2)
out_kernel(float* __restrict__ out)
{
    extern __shared__ char sm[];
    const uint32_t smb = smem_u32(sm);
    const int tid  = threadIdx.x;
    const int w    = tid >> 5;
    const int lane = tid & 31;
    const int gid  = lane >> 2;
    const int tig  = lane & 3;
    const int b    = blockIdx.z;
    const int ty0  = blockIdx.y * 8;
    const int tx0  = blockIdx.x * 32;

    float acc[2][4][4];
    #pragma unroll
    for (int mt = 0; mt < 2; mt++)
        #pragma unroll
        for (int n = 0; n < 4; n++)
            #pragma unroll
            for (int q = 0; q < 4; q++) acc[mt][n][q] = 0.f;

    const int hbase = (w + 1) * 34 + 1;
    const uint32_t laneA0 = smb + (uint32_t)(hbase + (lane & 15)) * RS
                          + (uint32_t)((lane >> 4) << 4);

    stage_A(sm, smb, 0, 3, b, ty0, tx0, tid);
    CP_COMMIT();
    CP_WAIT0();
    __syncthreads();

    const uint4* Bp = g_BfragOut + lane;
    conv_tap_loop(acc, laneA0, laneA0 + 16u*RS, Bp);

    #pragma unroll
    for (int mt = 0; mt < 2; mt++) {
        #pragma unroll
        for (int hf = 0; hf < 2; hf++) {
            int px_local = mt*16 + gid + hf*8;
            int py = ty0 + w;
            int px = tx0 + px_local;
            size_t pidx = (size_t)b * CHW + (size_t)py * Ww + px;
            #pragma unroll
            for (int n = 0; n < 4; n++) {
                #pragma unroll
                for (int q = 0; q < 2; q++) {
                    int co  = n*8 + 2*tig + q;
                    float v = acc[mt][n][hf*2 + q] + g_bout[co];
                    out[pidx + (size_t)co * HW] = fast_tanh(v);
                }
            }
        }
    }
}

extern "C" void kernel_launch(void* const* d_in, const int* in_sizes, int n_in,
                              void* d_out, int out_size)
{
    (void)in_sizes; (void)n_in; (void)out_size;
    const float* x  = (const float*)d_in[0];
    const float* he = (const float*)d_in[1];
    const float* hi = (const float*)d_in[2];
    float* out = (float*)d_out;

    cudaFuncSetAttribute(state_kernel, cudaFuncAttributeMaxDynamicSharedMemorySize, SMEM_T);
    cudaFuncSetAttribute(out_kernel,   cudaFuncAttributeMaxDynamicSharedMemorySize, A_SZ);

    prep_kernel<<<32, 256>>>(
        (const float*)d_in[3],  (const float*)d_in[4],
        (const float*)d_in[5],  (const float*)d_in[6],
        (const float*)d_in[7],  (const float*)d_in[8],
        (const float*)d_in[9],  (const float*)d_in[10],
        (const float*)d_in[11], (const float*)d_in[12],
        (const float*)d_in[13], (const float*)d_in[14],
        (const float*)d_in[15], (const float*)d_in[16],
        (const float*)d_in[17], (const float*)d_in[18]);

    convert_kernel<<<(3*Bn*HW)/256, 256>>>(x, he, hi);

    dim3 gs(4, 16, Bn*2);   // x-tiles, y-tiles, batch x co-half
    state_kernel<<<gs, THREADS, SMEM_T>>>(he, hi, out);
    dim3 go(4, 16, Bn);
    out_kernel<<<go, THREADS, A_SZ>>>(out);
}

// round 17
// speedup vs baseline: 2.2170x; 1.0697x over previous
#include <cuda_runtime.h>
#include <math.h>
#include <stdint.h>

#define Bn 16
#define Cc 32
#define Hh 128
#define Ww 128
#define HW (Hh*Ww)
#define CHW (Cc*HW)
#define NTOT (Bn*CHW)

// block tile: 8 out rows x 32 out cols = 256 px; halo 10x34 = 340 A rows
#define THREADS 256
#define NROWS 340

#define RS     80                     // SMEM row stride: 64B fp16 data + 16 pad
#define A_SZ   (NROWS*RS)             // 27200 bytes per buffer
#define SMEM_T (2*A_SZ)               // 54400: double-buffered A

// global A-row images: [t(4)][b*HW + pix] rows of 64B (32ci fp16), dense
__device__ uint4 g_Arows[(size_t)4*Bn*HW*4];

// B fragment tables (single fp16 plane), register-image order:
// state: [t(3)][half(2)][tap(9)][s(2)][p(2)][lane(32)] -> 6912 uint4
// out:   [tap(9)][s(2)][p(2)][lane(32)]                -> 1152 uint4
#define STFRAG (3*2*9*2*2*32)
#define OUTFRAG (9*2*2*32)
__device__ __align__(16) uint4 g_BfragSt[STFRAG];
__device__ __align__(16) uint4 g_BfragOut[OUTFRAG];
__device__ float g_bcomb[64];
__device__ float g_bout[32];
__device__ float g_invtau[64];

// ---------------- helpers ----------------
__device__ __forceinline__ uint32_t smem_u32(const void* p) {
    uint32_t a;
    asm("{ .reg .u64 t; cvta.to.shared.u64 t, %1; cvt.u32.u64 %0, t; }" : "=r"(a) : "l"(p));
    return a;
}
__device__ __forceinline__ unsigned short f2h(float v) {
    unsigned short h;
    asm("cvt.rn.f16.f32 %0, %1;" : "=h"(h) : "f"(v));
    return h;
}
__device__ __forceinline__ float fast_tanh(float x) {
    float e, r;
    asm("ex2.approx.f32 %0, %1;" : "=f"(e) : "f"(x * 2.8853900817779268f));
    asm("rcp.approx.f32 %0, %1;" : "=f"(r) : "f"(e + 1.f));
    return fmaf(-2.f, r, 1.f);
}
__device__ __forceinline__ void mma16816(float* c,
    uint32_t a0, uint32_t a1, uint32_t a2, uint32_t a3, uint32_t b0, uint32_t b1)
{
    asm volatile(
        "mma.sync.aligned.m16n8k16.row.col.f32.f16.f16.f32 "
        "{%0,%1,%2,%3}, {%4,%5,%6,%7}, {%8,%9}, {%0,%1,%2,%3};"
        : "+f"(c[0]), "+f"(c[1]), "+f"(c[2]), "+f"(c[3])
        : "r"(a0), "r"(a1), "r"(a2), "r"(a3), "r"(b0), "r"(b1));
}
__device__ __forceinline__ void ldsm4(uint32_t* r, uint32_t addr) {
    asm volatile("ldmatrix.sync.aligned.m8n8.x4.shared.b16 {%0,%1,%2,%3}, [%4];"
        : "=r"(r[0]), "=r"(r[1]), "=r"(r[2]), "=r"(r[3]) : "r"(addr));
}
__device__ __forceinline__ void cp16(uint32_t smdst, const void* gsrc) {
    asm volatile("cp.async.cg.shared.global [%0], [%1], 16;" :: "r"(smdst), "l"(gsrc));
}
#define CP_COMMIT() asm volatile("cp.async.commit_group;" ::: "memory")
#define CP_WAIT0()  asm volatile("cp.async.wait_group 0;" ::: "memory")
#define CP_WAIT1()  asm volatile("cp.async.wait_group 1;" ::: "memory")

// ---------------- prep: Dale fold, plain fp16 weights, FRAGMENT order ----------------
__global__ void prep_kernel(
    const float* __restrict__ W_in_e, const float* __restrict__ b_in_e,
    const float* __restrict__ W_in_i, const float* __restrict__ b_in_i,
    const float* __restrict__ W_e_e,  const float* __restrict__ b_e_e,
    const float* __restrict__ W_e_i,  const float* __restrict__ b_e_i,
    const float* __restrict__ W_e_out,const float* __restrict__ b_e_out,
    const float* __restrict__ W_i_e,  const float* __restrict__ b_i_e,
    const float* __restrict__ W_i_i,  const float* __restrict__ b_i_i,
    const float* __restrict__ tau_e,  const float* __restrict__ tau_i)
{
    int fid = blockIdx.x * 256 + threadIdx.x;
    if (fid < STFRAG) {
        int lane = fid & 31;
        int q    = fid >> 5;
        int p     = q & 1;  q >>= 1;
        int s     = q & 1;  q >>= 1;
        int tap   = q % 9;  q /= 9;
        int half  = q & 1;
        int t     = q >> 1;
        uint32_t comp[4];
        #pragma unroll
        for (int j = 0; j < 4; j++) {
            int co_l = p*16 + ((j>>1)<<3) + (lane>>2);
            int ci   = s*16 + ((j&1)<<3) + ((lane&3)<<1);
            unsigned short v[2];
            #pragma unroll
            for (int e = 0; e < 2; e++) {
                int src = co_l * 288 + (ci + e) * 9 + tap;   // OIHW
                float w;
                if (t == 0)      w = (half == 0) ? W_in_e[src] : W_in_i[src];
                else if (t == 1) w = fmaxf((half == 0) ? W_e_e[src] : W_e_i[src], 0.f);
                else             w = -fmaxf((half == 0) ? W_i_e[src] : W_i_i[src], 0.f);
                v[e] = f2h(w);
            }
            comp[j] = (uint32_t)v[0] | ((uint32_t)v[1] << 16);
        }
        g_BfragSt[fid] = make_uint4(comp[0], comp[1], comp[2], comp[3]);
    } else if (fid < STFRAG + OUTFRAG) {
        int f2   = fid - STFRAG;
        int lane = f2 & 31;
        int q    = f2 >> 5;
        int p     = q & 1;  q >>= 1;
        int s     = q & 1;  q >>= 1;
        int tap   = q;
        uint32_t comp[4];
        #pragma unroll
        for (int j = 0; j < 4; j++) {
            int co_l = p*16 + ((j>>1)<<3) + (lane>>2);
            int ci   = s*16 + ((j&1)<<3) + ((lane&3)<<1);
            unsigned short v[2];
            #pragma unroll
            for (int e = 0; e < 2; e++)
                v[e] = f2h(fmaxf(W_e_out[co_l*288 + (ci + e)*9 + tap], 0.f));
            comp[j] = (uint32_t)v[0] | ((uint32_t)v[1] << 16);
        }
        g_BfragOut[f2] = make_uint4(comp[0], comp[1], comp[2], comp[3]);
    }
    if (blockIdx.x == 0 && threadIdx.x < 64) {
        int co = threadIdx.x;
        if (co < 32) {
            g_bcomb[co]  = b_in_e[co] + fmaxf(b_e_e[co], 0.f) - fmaxf(b_i_e[co], 0.f);
            g_invtau[co] = 1.f / fmaxf(tau_e[co], 1.f);
            g_bout[co]   = fmaxf(b_e_out[co], 0.f);
        } else {
            int c = co - 32;
            g_bcomb[co]  = b_in_i[c] + fmaxf(b_e_i[c], 0.f) - fmaxf(b_i_i[c], 0.f);
            g_invtau[co] = 1.f / fmaxf(tau_i[c], 1.f);
        }
    }
}

// ---------------- convert: NCHW fp32 -> per-pixel 64B fp16 rows ----------------
__global__ void __launch_bounds__(256)
convert_kernel(const float* __restrict__ x, const float* __restrict__ he,
               const float* __restrict__ hi)
{
    int gidx = blockIdx.x * 256 + threadIdx.x;
    int t = gidx / (Bn*HW);
    int p = gidx - t * (Bn*HW);
    int b = p / HW;
    int pix = p - b * HW;
    const float* src = (t == 0 ? x : (t == 1 ? he : hi)) + (size_t)b * CHW + pix;
    uint4* dst = g_Arows + ((size_t)t * (Bn*HW) + p) * 4;

    uint32_t hw[16];
    #pragma unroll
    for (int k = 0; k < 16; k++) {
        unsigned short h0 = f2h(src[(size_t)(2*k)   * HW]);
        unsigned short h1 = f2h(src[(size_t)(2*k+1) * HW]);
        hw[k] = (uint32_t)h0 | ((uint32_t)h1 << 16);
    }
    #pragma unroll
    for (int j = 0; j < 4; j++)
        dst[j] = make_uint4(hw[4*j], hw[4*j+1], hw[4*j+2], hw[4*j+3]);
}

// ---------------- A tile staging: 64B rows, division-free ----------------
__device__ __forceinline__ void stage_A(char* sm, uint32_t smb, uint32_t a_off,
                                        int t, int b, int ty0, int tx0, int tid)
{
    const char* gb = (const char*)g_Arows + ((size_t)t * (Bn*HW) + (size_t)b * HW) * 64;
    const int c   = tid & 3;
    const int col = tid >> 2;
    if (col >= 34) return;

    const int gx   = tx0 + col - 1;
    const bool okx = ((unsigned)gx < 128u);
    uint32_t dst = smb + a_off + (uint32_t)col * RS + (uint32_t)c * 16;
    const char* src = gb + ((size_t)(ty0 - 1) * Ww + gx) * 64 + c * 16;

    #pragma unroll
    for (int ry = 0; ry < 10; ry++) {
        const int gy = ty0 + ry - 1;
        if (((unsigned)gy < 128u) && okx) cp16(dst, src);
        else                              *(uint4*)(sm + (dst - smb)) = make_uint4(0,0,0,0);
        dst += 34u * RS;
        src += (size_t)Ww * 64;
    }
}

// load a tap's 4 B fragments for one half (flat reg image: [g(s*2+p)][4])
__device__ __forceinline__ void load_B(const uint4* __restrict__ bp, uint32_t* bf) {
    #pragma unroll
    for (int g = 0; g < 4; g++) {
        uint4 qv = bp[(size_t)g * 32];
        bf[g*4+0] = qv.x; bf[g*4+1] = qv.y; bf[g*4+2] = qv.z; bf[g*4+3] = qv.w;
    }
}

// ---------------- state kernel (full N=64 per block; double-buffered A pipeline) ----------------
__global__ void __launch_bounds__(THREADS, 2)
state_kernel(const float* __restrict__ he, const float* __restrict__ hi,
             float* __restrict__ out)
{
    extern __shared__ char sm[];
    const uint32_t smb = smem_u32(sm);
    const int tid  = threadIdx.x;
    const int w    = tid >> 5;
    const int lane = tid & 31;
    const int gid  = lane >> 2;
    const int tig  = lane & 3;
    const int b    = blockIdx.z;
    const int ty0  = blockIdx.y * 8;
    const int tx0  = blockIdx.x * 32;

    float acc[2][8][4];   // [mt][half*4 + n][quad]
    #pragma unroll
    for (int mt = 0; mt < 2; mt++)
        #pragma unroll
        for (int n = 0; n < 8; n++)
            #pragma unroll
            for (int q = 0; q < 4; q++) acc[mt][n][q] = 0.f;

    const int hbase = (w + 1) * 34 + 1;
    const uint32_t laneA0b = smb + (uint32_t)(hbase + (lane & 15)) * RS
                           + (uint32_t)((lane >> 4) << 4);

    stage_A(sm, smb, 0, 0, b, ty0, tx0, tid);
    CP_COMMIT();

    #pragma unroll 1
    for (int t = 0; t < 3; t++) {
        if (t < 2) {
            stage_A(sm, smb, (uint32_t)((t + 1) & 1) * A_SZ, t + 1, b, ty0, tx0, tid);
            CP_COMMIT();
            CP_WAIT1();
        } else {
            CP_WAIT0();
        }
        __syncthreads();

        const uint32_t laneA0 = laneA0b + (uint32_t)(t & 1) * A_SZ;
        const uint32_t laneA1 = laneA0 + 16u*RS;
        const uint4* Bp0 = g_BfragSt + ((size_t)(t*2 + 0) * 9) * 128 + lane;
        const uint4* Bp1 = g_BfragSt + ((size_t)(t*2 + 1) * 9) * 128 + lane;

        #pragma unroll
        for (int tap = 0; tap < 9; tap++) {
            const int soff = ((tap/3) - 1) * (34*RS) + ((tap % 3) - 1) * RS;
            uint32_t Aa[2][2][4];
            ldsm4(Aa[0][0], laneA0 + soff + 0);  ldsm4(Aa[0][1], laneA0 + soff + 32);
            ldsm4(Aa[1][0], laneA1 + soff + 0);  ldsm4(Aa[1][1], laneA1 + soff + 32);

            #pragma unroll
            for (int half = 0; half < 2; half++) {
                uint32_t B[16];
                load_B((half ? Bp1 : Bp0) + (size_t)tap * 128, B);
                #pragma unroll
                for (int s = 0; s < 2; s++) {
                    const uint32_t* bb = B + s*8;   // [p(2)][4]
                    #pragma unroll
                    for (int mt = 0; mt < 2; mt++)
                        #pragma unroll
                        for (int n = 0; n < 4; n++) {
                            const int p = n >> 1, q = (n & 1) * 2;
                            mma16816(acc[mt][half*4 + n],
                                     Aa[mt][s][0], Aa[mt][s][1], Aa[mt][s][2], Aa[mt][s][3],
                                     bb[p*4 + q], bb[p*4 + q + 1]);
                        }
                }
            }
        }
        __syncthreads();
    }

    // epilogue: bias, tanh, leaky integrate; emit h_e_new fp16 rows
    uint32_t* rowbase = (uint32_t*)(g_Arows + (size_t)3 * (Bn*HW) * 4);
    #pragma unroll
    for (int mt = 0; mt < 2; mt++) {
        #pragma unroll
        for (int hf = 0; hf < 2; hf++) {
            int px_local = mt*16 + gid + hf*8;
            int py = ty0 + w;
            int px = tx0 + px_local;
            size_t pidx = (size_t)b * CHW + (size_t)py * Ww + px;
            uint32_t* rp = rowbase + ((size_t)b * HW + (size_t)py * Ww + px) * 16;
            #pragma unroll
            for (int n = 0; n < 4; n++) {
                int cl = n*8 + 2*tig;
                // e-channels (half 0)
                {
                    float a0 = acc[mt][n][hf*2]     + g_bcomb[cl];
                    float a1 = acc[mt][n][hf*2 + 1] + g_bcomb[cl+1];
                    float i0 = g_invtau[cl], i1 = g_invtau[cl+1];
                    float c0 = fast_tanh(a0), c1 = fast_tanh(a1);
                    float h0 = (i0 < 1.f) ? he[pidx + (size_t)cl * HW]     : 0.f;
                    float h1 = (i1 < 1.f) ? he[pidx + (size_t)(cl+1) * HW] : 0.f;
                    float v0 = (1.f - i0)*h0 + i0*c0;
                    float v1 = (1.f - i1)*h1 + i1*c1;
                    out[(size_t)NTOT + pidx + (size_t)cl * HW]     = v0;
                    out[(size_t)NTOT + pidx + (size_t)(cl+1) * HW] = v1;
                    rp[cl >> 1] = (uint32_t)f2h(v0) | ((uint32_t)f2h(v1) << 16);
                }
                // i-channels (half 1)
                {
                    int co = 32 + cl;
                    float a0 = acc[mt][4 + n][hf*2]     + g_bcomb[co];
                    float a1 = acc[mt][4 + n][hf*2 + 1] + g_bcomb[co+1];
                    float i0 = g_invtau[co], i1 = g_invtau[co+1];
                    float c0 = fast_tanh(a0), c1 = fast_tanh(a1);
                    float h0 = (i0 < 1.f) ? hi[pidx + (size_t)cl * HW]     : 0.f;
                    float h1 = (i1 < 1.f) ? hi[pidx + (size_t)(cl+1) * HW] : 0.f;
                    out[(size_t)2*NTOT + pidx + (size_t)cl * HW]     = (1.f - i0)*h0 + i0*c0;
                    out[(size_t)2*NTOT + pidx + (size_t)(cl+1) * HW] = (1.f - i1)*h1 + i1*c1;
                }
            }
        }
    }
}

// ---------------- out kernel (unchanged round-16 form) ----------------
__global__ void __launch_bounds__(THREADS, 2)
out_kernel(float* __restrict__ out)
{
    extern __shared__ char sm[];
    const uint32_t smb = smem_u32(sm);
    const int tid  = threadIdx.x;
    const int w    = tid >> 5;
    const int lane = tid & 31;
    const int gid  = lane >> 2;
    const int tig  = lane & 3;
    const int b    = blockIdx.z;
    const int ty0  = blockIdx.y * 8;
    const int tx0  = blockIdx.x * 32;

    float acc[2][4][4];
    #pragma unroll
    for (int mt = 0; mt < 2; mt++)
        #pragma unroll
        for (int n = 0; n < 4; n++)
            #pragma unroll
            for (int q = 0; q < 4; q++) acc[mt][n][q] = 0.f;

    const int hbase = (w + 1) * 34 + 1;
    const uint32_t laneA0 = smb + (uint32_t)(hbase + (lane & 15)) * RS
                          + (uint32_t)((lane >> 4) << 4);
    const uint32_t laneA1 = laneA0 + 16u*RS;

    stage_A(sm, smb, 0, 3, b, ty0, tx0, tid);
    CP_COMMIT();
    CP_WAIT0();
    __syncthreads();

    const uint4* Bp = g_BfragOut + lane;
    uint32_t B[2][16];
    load_B(Bp, B[0]);
    #pragma unroll
    for (int tap = 0; tap < 9; tap++) {
        if (tap < 8) load_B(Bp + (size_t)(tap + 1) * 128, B[(tap + 1) & 1]);

        const int soff = ((tap/3) - 1) * (34*RS) + ((tap % 3) - 1) * RS;
        uint32_t Aa[2][2][4];
        ldsm4(Aa[0][0], laneA0 + soff + 0);  ldsm4(Aa[0][1], laneA0 + soff + 32);
        ldsm4(Aa[1][0], laneA1 + soff + 0);  ldsm4(Aa[1][1], laneA1 + soff + 32);

        const uint32_t* bc = B[tap & 1];
        #pragma unroll
        for (int s = 0; s < 2; s++) {
            const uint32_t* bb = bc + s*8;
            #pragma unroll
            for (int mt = 0; mt < 2; mt++)
                #pragma unroll
                for (int n = 0; n < 4; n++) {
                    const int p = n >> 1, q = (n & 1) * 2;
                    mma16816(acc[mt][n],
                             Aa[mt][s][0], Aa[mt][s][1], Aa[mt][s][2], Aa[mt][s][3],
                             bb[p*4 + q], bb[p*4 + q + 1]);
                }
        }
    }

    #pragma unroll
    for (int mt = 0; mt < 2; mt++) {
        #pragma unroll
        for (int hf = 0; hf < 2; hf++) {
            int px_local = mt*16 + gid + hf*8;
            int py = ty0 + w;
            int px = tx0 + px_local;
            size_t pidx = (size_t)b * CHW + (size_t)py * Ww + px;
            #pragma unroll
            for (int n = 0; n < 4; n++) {
                #pragma unroll
                for (int q = 0; q < 2; q++) {
                    int co  = n*8 + 2*tig + q;
                    float v = acc[mt][n][hf*2 + q] + g_bout[co];
                    out[pidx + (size_t)co * HW] = fast_tanh(v);
                }
            }
        }
    }
}

extern "C" void kernel_launch(void* const* d_in, const int* in_sizes, int n_in,
                              void* d_out, int out_size)
{
    (void)in_sizes; (void)n_in; (void)out_size;
    const float* x  = (const float*)d_in[0];
    const float* he = (const float*)d_in[1];
    const float* hi = (const float*)d_in[2];
    float* out = (float*)d_out;

    cudaFuncSetAttribute(state_kernel, cudaFuncAttributeMaxDynamicSharedMemorySize, SMEM_T);
    cudaFuncSetAttribute(out_kernel,   cudaFuncAttributeMaxDynamicSharedMemorySize, A_SZ);

    prep_kernel<<<32, 256>>>(
        (const float*)d_in[3],  (const float*)d_in[4],
        (const float*)d_in[5],  (const float*)d_in[6],
        (const float*)d_in[7],  (const float*)d_in[8],
        (const float*)d_in[9],  (const float*)d_in[10],
        (const float*)d_in[11], (const float*)d_in[12],
        (const float*)d_in[13], (const float*)d_in[14],
        (const float*)d_in[15], (const float*)d_in[16],
        (const float*)d_in[17], (const float*)d_in[18]);

    convert_kernel<<<(3*Bn*HW)/256, 256>>>(x, he, hi);

    dim3 gs(4, 16, Bn);   // x-tiles, y-tiles, batch (full 64-co blocks)
    state_kernel<<<gs, THREADS, SMEM_T>>>(he, hi, out);
    dim3 go(4, 16, Bn);
    out_kernel<<<go, THREADS, A_SZ>>>(out);
}